// round 1
// baseline (speedup 1.0000x reference)
#include <cuda_runtime.h>
#include <math.h>

// Problem constants (fixed by the dataset)
#define BB  2
#define HH  480
#define WW  640
#define HW1 (HH*WW)

// ---------------- scratch (static device memory; no allocations) ----------------
__device__ float g_xin [BB*6 *HW1];   // concat input per scale (B,6,Hs,Ws)
__device__ float g_f0  [BB*64*HW1];   // feature ping
__device__ float g_f1  [BB*64*HW1];   // feature pong
__device__ float g_aff [BB*24*HW1];   // raw affinity conv out
__device__ float g_gate[BB*3 *HW1];   // raw gate conv out
__device__ float g_curv[BB*3 *HW1];   // curv conv out (first 64 input channels only)
__device__ float g_coef[BB*26*HW1];   // fused propagation coefficients: c0, W[24], a
__device__ float g_D   [BB*HW1];
__device__ float g_D2  [BB*HW1];
__device__ float g_Dp  [BB*HW1];      // previous-scale result

// ============================================================================
// prep for s in {4,2}: antialiased triangle resize of I,E + valid-mean pool of
// sparse depth. Matches jax.image.resize(method='linear', antialias=True):
//   c = (i+0.5)*R - 0.5 ; w(j) = max(0, 1-|j-c|/R) over 2R taps, renormalized
//   over in-bounds taps.
// ============================================================================
template<int R>
__global__ void prep_scale_k(const float* __restrict__ I, const float* __restrict__ DL,
                             const float* __restrict__ ML, const float* __restrict__ E,
                             float* __restrict__ xin, float* __restrict__ Dout,
                             int Hs, int Ws, int writeD)
{
    int HWs = Hs*Ws;
    int idx = blockIdx.x*blockDim.x + threadIdx.x;
    if (idx >= BB*HWs) return;
    int b = idx / HWs, p = idx - b*HWs;
    int y = p / Ws,    x = p - y*Ws;

    float wy[2*R], wx[2*R];
    int   jy[2*R], jx[2*R];
    {
        float c = (y + 0.5f)*(float)R - 0.5f;
        int j0 = (int)ceilf(c - (float)R);
        float s = 0.f;
        #pragma unroll
        for (int t = 0; t < 2*R; ++t) {
            int j = j0 + t;
            float wt = 1.0f - fabsf((float)j - c)*(1.0f/(float)R);
            if (j < 0 || j >= HH || wt < 0.f) wt = 0.f;
            wy[t] = wt; s += wt;
            jy[t] = min(max(j,0), HH-1);
        }
        float inv = 1.0f/s;
        #pragma unroll
        for (int t = 0; t < 2*R; ++t) wy[t] *= inv;
    }
    {
        float c = (x + 0.5f)*(float)R - 0.5f;
        int j0 = (int)ceilf(c - (float)R);
        float s = 0.f;
        #pragma unroll
        for (int t = 0; t < 2*R; ++t) {
            int j = j0 + t;
            float wt = 1.0f - fabsf((float)j - c)*(1.0f/(float)R);
            if (j < 0 || j >= WW || wt < 0.f) wt = 0.f;
            wx[t] = wt; s += wt;
            jx[t] = min(max(j,0), WW-1);
        }
        float inv = 1.0f/s;
        #pragma unroll
        for (int t = 0; t < 2*R; ++t) wx[t] *= inv;
    }

    // I channels 0..2
    #pragma unroll
    for (int ch = 0; ch < 3; ++ch) {
        const float* src = I + (size_t)(b*3+ch)*HW1;
        float a = 0.f;
        #pragma unroll
        for (int ty = 0; ty < 2*R; ++ty) {
            if (wy[ty] == 0.f) continue;
            const float* row = src + jy[ty]*WW;
            float rs = 0.f;
            #pragma unroll
            for (int t = 0; t < 2*R; ++t) rs += wx[t]*row[jx[t]];
            a += wy[ty]*rs;
        }
        xin[(size_t)(b*6+ch)*HWs + p] = a;
    }
    // E (clipped)
    {
        const float* src = E + (size_t)b*HW1;
        float a = 0.f;
        #pragma unroll
        for (int ty = 0; ty < 2*R; ++ty) {
            if (wy[ty] == 0.f) continue;
            const float* row = src + jy[ty]*WW;
            float rs = 0.f;
            #pragma unroll
            for (int t = 0; t < 2*R; ++t) rs += wx[t]*row[jx[t]];
            a += wy[ty]*rs;
        }
        a = fminf(fmaxf(a, 0.f), 1.f);
        xin[(size_t)(b*6+5)*HWs + p] = a;
        if (writeD) Dout[(size_t)b*HWs + p] = fminf(fmaxf(a*10.f, 0.f), 10.f);
    }
    // down_sparse: valid-mean pool over R x R block
    {
        const float* dlb = DL + (size_t)b*HW1;
        const float* mlb = ML + (size_t)b*HW1;
        float ssum = 0.f, cnt = 0.f;
        #pragma unroll
        for (int iy = 0; iy < R; ++iy) {
            int gy = y*R + iy;
            #pragma unroll
            for (int ix = 0; ix < R; ++ix) {
                int gi = gy*WW + x*R + ix;
                float m = (mlb[gi] > 0.f) ? 1.f : 0.f;
                cnt  += m;
                ssum += dlb[gi]*m;
            }
        }
        float mls = (cnt > 0.f) ? 1.f : 0.f;
        float dls = (cnt > 0.f) ? ssum/(cnt + 1e-6f) : 0.f;
        xin[(size_t)(b*6+3)*HWs + p] = dls;
        xin[(size_t)(b*6+4)*HWs + p] = mls;
    }
}

// s==1: identity prep
__global__ void prep_copy_k(const float* __restrict__ I, const float* __restrict__ DL,
                            const float* __restrict__ ML, const float* __restrict__ E,
                            float* __restrict__ xin)
{
    int idx = blockIdx.x*blockDim.x + threadIdx.x;
    if (idx >= BB*HW1) return;
    int b = idx / HW1, p = idx - b*HW1;
    #pragma unroll
    for (int ch = 0; ch < 3; ++ch)
        xin[(size_t)(b*6+ch)*HW1 + p] = I[(size_t)(b*3+ch)*HW1 + p];
    xin[(size_t)(b*6+3)*HW1 + p] = DL[(size_t)b*HW1 + p];
    xin[(size_t)(b*6+4)*HW1 + p] = (ML[(size_t)b*HW1 + p] > 0.f) ? 1.f : 0.f;
    xin[(size_t)(b*6+5)*HW1 + p] = fminf(fmaxf(E[(size_t)b*HW1 + p], 0.f), 1.f);
}

// ============================================================================
// Edge-aware blend of upsampled previous-scale depth with P_s = 10*E_s
// (only for the 2nd and 3rd scales)
// ============================================================================
__global__ void blend_k(const float* __restrict__ xin, const float* __restrict__ Dprev,
                        float* __restrict__ D, int Hs, int Ws)
{
    int HWs = Hs*Ws;
    int idx = blockIdx.x*blockDim.x + threadIdx.x;
    if (idx >= BB*HWs) return;
    int b = idx / HWs, p = idx - b*HWs;
    int y = p / Ws,    x = p - y*Ws;

    const float* Ep = xin + (size_t)(b*6+5)*HWs;
    float e  = Ep[p];
    float gx = (x > 0) ? e - Ep[p-1]  : 0.f;
    float gy = (y > 0) ? e - Ep[p-Ws] : 0.f;
    float g  = fminf((fabsf(gx) + fabsf(gy))*0.5f, 1.f);
    float wgt = 0.7f * fminf(fmaxf(1.f - g*10.0f, 0.f), 1.f);

    int Hp = Hs >> 1, Wp = Ws >> 1;
    float cy = 0.5f*(float)y - 0.25f;
    int  jy0 = (int)floorf(cy); float fy = cy - (float)jy0;
    int  ya = max(jy0, 0), yb = min(jy0+1, Hp-1);
    float cx = 0.5f*(float)x - 0.25f;
    int  jx0 = (int)floorf(cx); float fx = cx - (float)jx0;
    int  xa = max(jx0, 0), xb = min(jx0+1, Wp-1);

    const float* Dp = Dprev + (size_t)b*Hp*Wp;
    float up = (1.f-fy)*((1.f-fx)*Dp[ya*Wp+xa] + fx*Dp[ya*Wp+xb])
             +       fy*((1.f-fx)*Dp[yb*Wp+xa] + fx*Dp[yb*Wp+xb]);
    float P = fminf(fmaxf(e*10.f, 0.f), 10.f);
    D[(size_t)b*HWs + p] = wgt*up + (1.f - wgt)*P;
}

// ============================================================================
// Generic 3x3 SAME conv, fp32. 64x32 output tile, 8 couts per block,
// per-thread: 8 couts x 2 cols x 4 rows accumulators.
// wCinStride lets curv_w (stride 65) reuse the CIN=64 instantiation.
// ============================================================================
template<int CIN, bool RELU>
__global__ __launch_bounds__(256, 2)
void conv3x3_k(const float* __restrict__ in, const float* __restrict__ wgt,
               const float* __restrict__ bias, float* __restrict__ out,
               int H, int W, int coutTotal, int wCinStride)
{
    const int nG = (coutTotal + 7) >> 3;
    const int b  = blockIdx.z / nG;
    const int cg = blockIdx.z % nG;
    const int x0 = blockIdx.x * 64;
    const int y0 = blockIdx.y * 32;
    const int HWl = H*W;

    __shared__ float s_in[34][66];
    __shared__ float s_w[8][9];

    const int tx  = threadIdx.x & 31;
    const int wy4 = (threadIdx.x >> 5) * 4;   // 0,4,...,28

    float acc[8][2][4];
    #pragma unroll
    for (int a = 0; a < 8; ++a)
        #pragma unroll
        for (int c = 0; c < 2; ++c)
            #pragma unroll
            for (int r = 0; r < 4; ++r) acc[a][c][r] = 0.f;

    const float* inB = in + (size_t)b * CIN * HWl;

    for (int ci = 0; ci < CIN; ++ci) {
        __syncthreads();
        const float* inC = inB + (size_t)ci * HWl;
        for (int i = threadIdx.x; i < 34*66; i += 256) {
            int yy = i / 66, xx = i - yy*66;
            int gy = y0 + yy - 1, gx = x0 + xx - 1;
            float v = 0.f;
            if ((unsigned)gy < (unsigned)H && (unsigned)gx < (unsigned)W)
                v = inC[gy*W + gx];
            s_in[yy][xx] = v;
        }
        if (threadIdx.x < 72) {
            int co = threadIdx.x / 9, t = threadIdx.x - co*9;
            int cout = cg*8 + co;
            s_w[co][t] = (cout < coutTotal)
                       ? wgt[((size_t)cout*wCinStride + ci)*9 + t] : 0.f;
        }
        __syncthreads();

        #pragma unroll
        for (int ky = 0; ky < 3; ++ky)
            #pragma unroll
            for (int kx = 0; kx < 3; ++kx) {
                float wv[8];
                #pragma unroll
                for (int co = 0; co < 8; ++co) wv[co] = s_w[co][ky*3+kx];
                #pragma unroll
                for (int col = 0; col < 2; ++col) {
                    float v0 = s_in[wy4+ky+0][tx + col*32 + kx];
                    float v1 = s_in[wy4+ky+1][tx + col*32 + kx];
                    float v2 = s_in[wy4+ky+2][tx + col*32 + kx];
                    float v3 = s_in[wy4+ky+3][tx + col*32 + kx];
                    #pragma unroll
                    for (int co = 0; co < 8; ++co) {
                        acc[co][col][0] = fmaf(wv[co], v0, acc[co][col][0]);
                        acc[co][col][1] = fmaf(wv[co], v1, acc[co][col][1]);
                        acc[co][col][2] = fmaf(wv[co], v2, acc[co][col][2]);
                        acc[co][col][3] = fmaf(wv[co], v3, acc[co][col][3]);
                    }
                }
            }
    }

    #pragma unroll
    for (int co = 0; co < 8; ++co) {
        int cout = cg*8 + co;
        if (cout >= coutTotal) break;
        float bb = bias[cout];
        float* outC = out + ((size_t)b*coutTotal + cout)*HWl;
        #pragma unroll
        for (int col = 0; col < 2; ++col) {
            int gx = x0 + tx + col*32;
            if (gx >= W) continue;
            #pragma unroll
            for (int r = 0; r < 4; ++r) {
                int gy = y0 + wy4 + r;
                if (gy >= H) continue;
                float v = acc[co][col][r] + bb;
                if (RELU) v = fmaxf(v, 0.f);
                outC[gy*W + gx] = v;
            }
        }
    }
}

// ============================================================================
// Post-process heads -> fused step-invariant propagation coefficients.
//  mix = D + sum_k sigma_k*kappa_k * sum_j A_kj*(nb_kj - D)
//  D'  = (1-0.9ML)*mix + 0.9*ML*DL
//  => D' = c0*D + sum_24 W*nb + a  with
//  W = (1-0.9ML)*sk*A,  c0 = (1-0.9ML)*(1-sum W_raw),  a = 0.9*ML*DL
// kappa conv gets its 65th input channel (D/10) contribution added here.
// ============================================================================
__global__ void postproc_k(const float* __restrict__ aff, const float* __restrict__ gate,
                           const float* __restrict__ curvp, const float* __restrict__ cw,
                           const float* __restrict__ xin, const float* __restrict__ D,
                           float* __restrict__ coef, int Hs, int Ws)
{
    int HWs = Hs*Ws;
    int idx = blockIdx.x*blockDim.x + threadIdx.x;
    if (idx >= BB*HWs) return;
    int b = idx / HWs, p = idx - b*HWs;
    int y = p / Ws,    x = p - y*Ws;

    float An[24];
    #pragma unroll
    for (int k = 0; k < 3; ++k) {
        float s1 = 0.f;
        #pragma unroll
        for (int j = 0; j < 8; ++j) {
            float v = aff[(size_t)(b*24 + k*8 + j)*HWs + p];
            An[k*8+j] = v;
            s1 += fabsf(v);
        }
        float inv = 1.0f/(s1 + 1e-6f);
        #pragma unroll
        for (int j = 0; j < 8; ++j) An[k*8+j] *= inv;
    }

    float g0 = gate[(size_t)(b*3+0)*HWs + p];
    float g1 = gate[(size_t)(b*3+1)*HWs + p];
    float g2 = gate[(size_t)(b*3+2)*HWs + p];
    float mx = fmaxf(g0, fmaxf(g1, g2));
    float e0 = expf(g0-mx), e1 = expf(g1-mx), e2 = expf(g2-mx);
    float einv = 1.0f/(e0+e1+e2);
    float sig[3] = {e0*einv, e1*einv, e2*einv};

    const float* Db = D + (size_t)b*HWs;
    float sk[3];
    #pragma unroll
    for (int k = 0; k < 3; ++k) {
        float cr = curvp[(size_t)(b*3+k)*HWs + p];
        #pragma unroll
        for (int ky = 0; ky < 3; ++ky) {
            int yy = y + ky - 1;
            if (yy < 0 || yy >= Hs) continue;
            #pragma unroll
            for (int kx = 0; kx < 3; ++kx) {
                int xx = x + kx - 1;
                if (xx < 0 || xx >= Ws) continue;
                cr += cw[(size_t)(k*65 + 64)*9 + ky*3 + kx] * (Db[yy*Ws + xx]*0.1f);
            }
        }
        float kap = 0.1f + 0.9f/(1.0f + expf(-cr));
        sk[k] = sig[k]*kap;
    }

    float mls = xin[(size_t)(b*6+4)*HWs + p];
    float dls = xin[(size_t)(b*6+3)*HWs + p];
    float m   = 0.9f*mls;
    float one = 1.0f - m;
    float Wsum = 0.f;
    #pragma unroll
    for (int k = 0; k < 3; ++k)
        #pragma unroll
        for (int j = 0; j < 8; ++j) {
            float Wv = sk[k]*An[k*8+j];
            Wsum += Wv;
            coef[(size_t)(b*26 + 1 + k*8 + j)*HWs + p] = one*Wv;
        }
    coef[(size_t)(b*26)*HWs + p]      = one*(1.0f - Wsum);
    coef[(size_t)(b*26 + 25)*HWs + p] = m*dls;
}

// ============================================================================
// One propagation step: 25-tap stencil with precomputed coefficients.
// Neighbors outside the image are zero (matches zero-padded shift2d).
// ============================================================================
__global__ void prop_k(const float* __restrict__ Din, const float* __restrict__ coef,
                       float* __restrict__ Dout, int Hs, int Ws)
{
    __shared__ float sD[24][40];
    const int b  = blockIdx.z;
    const int x0 = blockIdx.x*32, y0 = blockIdx.y*16;
    const int HWs = Hs*Ws;
    const float* Db = Din + (size_t)b*HWs;

    int tid = threadIdx.y*32 + threadIdx.x;
    for (int i = tid; i < 24*40; i += 512) {
        int yy = i / 40, xx = i - yy*40;
        int gy = y0 + yy - 4, gx = x0 + xx - 4;
        sD[yy][xx] = ((unsigned)gy < (unsigned)Hs && (unsigned)gx < (unsigned)Ws)
                   ? Db[gy*Ws + gx] : 0.f;
    }
    __syncthreads();

    int x = x0 + threadIdx.x, y = y0 + threadIdx.y;
    if (x >= Ws || y >= Hs) return;
    int p = y*Ws + x;
    const float* cf = coef + (size_t)b*26*HWs;

    const int dyo[8] = {-1,-1,-1, 0, 0, 1, 1, 1};
    const int dxo[8] = {-1, 0, 1,-1, 1,-1, 0, 1};

    float acc = cf[p] * sD[threadIdx.y+4][threadIdx.x+4];
    #pragma unroll
    for (int k = 0; k < 3; ++k) {
        int d = 1 << k;   // dilations 1,2,4
        #pragma unroll
        for (int j = 0; j < 8; ++j) {
            acc = fmaf(cf[(size_t)(1 + k*8 + j)*HWs + p],
                       sD[threadIdx.y + 4 + dyo[j]*d][threadIdx.x + 4 + dxo[j]*d],
                       acc);
        }
    }
    Dout[(size_t)b*HWs + p] = acc + cf[(size_t)25*HWs + p];
}

// ============================================================================
extern "C" void kernel_launch(void* const* d_in, const int* in_sizes, int n_in,
                              void* d_out, int out_size)
{
    const float* I   = (const float*)d_in[0];
    const float* DL  = (const float*)d_in[1];
    const float* ML  = (const float*)d_in[2];
    const float* E   = (const float*)d_in[3];
    const float* ew0 = (const float*)d_in[4];
    const float* eb0 = (const float*)d_in[5];
    const float* ew1 = (const float*)d_in[6];
    const float* eb1 = (const float*)d_in[7];
    const float* ew2 = (const float*)d_in[8];
    const float* eb2 = (const float*)d_in[9];
    const float* aw  = (const float*)d_in[10];
    const float* ab  = (const float*)d_in[11];
    const float* gw  = (const float*)d_in[12];
    const float* gb  = (const float*)d_in[13];
    const float* cw  = (const float*)d_in[14];
    const float* cbp = (const float*)d_in[15];

    float *xin, *f0, *f1, *aff, *gate, *curv, *coef, *Db, *D2, *Dp;
    cudaGetSymbolAddress((void**)&xin,  g_xin);
    cudaGetSymbolAddress((void**)&f0,   g_f0);
    cudaGetSymbolAddress((void**)&f1,   g_f1);
    cudaGetSymbolAddress((void**)&aff,  g_aff);
    cudaGetSymbolAddress((void**)&gate, g_gate);
    cudaGetSymbolAddress((void**)&curv, g_curv);
    cudaGetSymbolAddress((void**)&coef, g_coef);
    cudaGetSymbolAddress((void**)&Db,   g_D);
    cudaGetSymbolAddress((void**)&D2,   g_D2);
    cudaGetSymbolAddress((void**)&Dp,   g_Dp);

    const int scales[3] = {4, 2, 1};
    for (int si = 0; si < 3; ++si) {
        int s = scales[si];
        int Hs = HH / s, Ws = WW / s, HWs = Hs*Ws;
        int n = BB*HWs;
        int tpb = 256, nb = (n + tpb - 1)/tpb;

        if (si > 0) {
            int sp = scales[si-1];
            cudaMemcpyAsync(Dp, Db, sizeof(float)*(size_t)BB*(HH/sp)*(WW/sp),
                            cudaMemcpyDeviceToDevice);
        }

        if (s == 4)      prep_scale_k<4><<<nb, tpb>>>(I, DL, ML, E, xin, Db, Hs, Ws, 1);
        else if (s == 2) prep_scale_k<2><<<nb, tpb>>>(I, DL, ML, E, xin, Db, Hs, Ws, 0);
        else             prep_copy_k<<<nb, tpb>>>(I, DL, ML, E, xin);

        if (si > 0) blend_k<<<nb, tpb>>>(xin, Dp, Db, Hs, Ws);

        dim3 blk(256);
        dim3 cgMain((Ws+63)/64, (Hs+31)/32, BB*8);
        conv3x3_k<6,  true ><<<cgMain, blk>>>(xin, ew0, eb0, f0, Hs, Ws, 64, 6);
        conv3x3_k<64, true ><<<cgMain, blk>>>(f0,  ew1, eb1, f1, Hs, Ws, 64, 64);
        conv3x3_k<64, true ><<<cgMain, blk>>>(f1,  ew2, eb2, f0, Hs, Ws, 64, 64);
        dim3 cgAff((Ws+63)/64, (Hs+31)/32, BB*3);
        conv3x3_k<64, false><<<cgAff,  blk>>>(f0, aw, ab, aff,  Hs, Ws, 24, 64);
        dim3 cgHead((Ws+63)/64, (Hs+31)/32, BB*1);
        conv3x3_k<64, false><<<cgHead, blk>>>(f0, gw, gb, gate, Hs, Ws, 3, 64);
        conv3x3_k<64, false><<<cgHead, blk>>>(f0, cw, cbp, curv, Hs, Ws, 3, 65);

        postproc_k<<<nb, tpb>>>(aff, gate, curv, cw, xin, Db, coef, Hs, Ws);

        dim3 pb(32, 16);
        dim3 pg((Ws+31)/32, (Hs+15)/16, BB);
        for (int t = 0; t < 6; ++t) {
            const float* src = (t & 1) ? D2 : Db;
            float*       dst = (t & 1) ? Db : D2;
            prop_k<<<pg, pb>>>(src, coef, dst, Hs, Ws);
        }
        // after an even number of steps the result is back in Db
    }

    cudaMemcpyAsync(d_out, Db, sizeof(float)*(size_t)BB*HW1, cudaMemcpyDeviceToDevice);
}

// round 3
// speedup vs baseline: 1.1488x; 1.1488x over previous
#include <cuda_runtime.h>
#include <math.h>

// Problem constants (fixed by the dataset)
#define BB  2
#define HH  480
#define WW  640
#define HW1 (HH*WW)

typedef unsigned long long ull;

__device__ __forceinline__ void fma2(ull& d, ull a, ull b){
    asm("fma.rn.f32x2 %0, %1, %2, %0;" : "+l"(d) : "l"(a), "l"(b));
}
__device__ __forceinline__ ull pack2(float lo, float hi){
    ull r; asm("mov.b64 %0, {%1, %2};" : "=l"(r) : "f"(lo), "f"(hi)); return r;
}
__device__ __forceinline__ float2 unpack2(ull v){
    float2 r; asm("mov.b64 {%0, %1}, %2;" : "=f"(r.x), "=f"(r.y) : "l"(v)); return r;
}

// ---------------- scratch (static device memory; no allocations) ----------------
__device__ float g_xin [BB*6 *HW1];
__device__ float g_f0  [BB*64*HW1];
__device__ float g_f1  [BB*64*HW1];
__device__ float g_aff [BB*24*HW1];
__device__ float g_gate[BB*3 *HW1];
__device__ float g_curv[BB*3 *HW1];
__device__ float g_coef[BB*26*HW1];
__device__ float g_D   [BB*HW1];
__device__ float g_D2  [BB*HW1];
__device__ float g_Dp  [BB*HW1];

// ============================================================================
// prep for s in {4,2}: antialiased triangle resize of I,E + valid-mean pool
// ============================================================================
template<int R>
__global__ void prep_scale_k(const float* __restrict__ I, const float* __restrict__ DL,
                             const float* __restrict__ ML, const float* __restrict__ E,
                             float* __restrict__ xin, float* __restrict__ Dout,
                             int Hs, int Ws, int writeD)
{
    int HWs = Hs*Ws;
    int idx = blockIdx.x*blockDim.x + threadIdx.x;
    if (idx >= BB*HWs) return;
    int b = idx / HWs, p = idx - b*HWs;
    int y = p / Ws,    x = p - y*Ws;

    float wy[2*R], wx[2*R];
    int   jy[2*R], jx[2*R];
    {
        float c = (y + 0.5f)*(float)R - 0.5f;
        int j0 = (int)ceilf(c - (float)R);
        float s = 0.f;
        #pragma unroll
        for (int t = 0; t < 2*R; ++t) {
            int j = j0 + t;
            float wt = 1.0f - fabsf((float)j - c)*(1.0f/(float)R);
            if (j < 0 || j >= HH || wt < 0.f) wt = 0.f;
            wy[t] = wt; s += wt;
            jy[t] = min(max(j,0), HH-1);
        }
        float inv = 1.0f/s;
        #pragma unroll
        for (int t = 0; t < 2*R; ++t) wy[t] *= inv;
    }
    {
        float c = (x + 0.5f)*(float)R - 0.5f;
        int j0 = (int)ceilf(c - (float)R);
        float s = 0.f;
        #pragma unroll
        for (int t = 0; t < 2*R; ++t) {
            int j = j0 + t;
            float wt = 1.0f - fabsf((float)j - c)*(1.0f/(float)R);
            if (j < 0 || j >= WW || wt < 0.f) wt = 0.f;
            wx[t] = wt; s += wt;
            jx[t] = min(max(j,0), WW-1);
        }
        float inv = 1.0f/s;
        #pragma unroll
        for (int t = 0; t < 2*R; ++t) wx[t] *= inv;
    }

    #pragma unroll
    for (int ch = 0; ch < 3; ++ch) {
        const float* src = I + (size_t)(b*3+ch)*HW1;
        float a = 0.f;
        #pragma unroll
        for (int ty = 0; ty < 2*R; ++ty) {
            if (wy[ty] == 0.f) continue;
            const float* row = src + jy[ty]*WW;
            float rs = 0.f;
            #pragma unroll
            for (int t = 0; t < 2*R; ++t) rs += wx[t]*row[jx[t]];
            a += wy[ty]*rs;
        }
        xin[(size_t)(b*6+ch)*HWs + p] = a;
    }
    {
        const float* src = E + (size_t)b*HW1;
        float a = 0.f;
        #pragma unroll
        for (int ty = 0; ty < 2*R; ++ty) {
            if (wy[ty] == 0.f) continue;
            const float* row = src + jy[ty]*WW;
            float rs = 0.f;
            #pragma unroll
            for (int t = 0; t < 2*R; ++t) rs += wx[t]*row[jx[t]];
            a += wy[ty]*rs;
        }
        a = fminf(fmaxf(a, 0.f), 1.f);
        xin[(size_t)(b*6+5)*HWs + p] = a;
        if (writeD) Dout[(size_t)b*HWs + p] = fminf(fmaxf(a*10.f, 0.f), 10.f);
    }
    {
        const float* dlb = DL + (size_t)b*HW1;
        const float* mlb = ML + (size_t)b*HW1;
        float ssum = 0.f, cnt = 0.f;
        #pragma unroll
        for (int iy = 0; iy < R; ++iy) {
            int gy = y*R + iy;
            #pragma unroll
            for (int ix = 0; ix < R; ++ix) {
                int gi = gy*WW + x*R + ix;
                float m = (mlb[gi] > 0.f) ? 1.f : 0.f;
                cnt  += m;
                ssum += dlb[gi]*m;
            }
        }
        float mls = (cnt > 0.f) ? 1.f : 0.f;
        float dls = (cnt > 0.f) ? ssum/(cnt + 1e-6f) : 0.f;
        xin[(size_t)(b*6+3)*HWs + p] = dls;
        xin[(size_t)(b*6+4)*HWs + p] = mls;
    }
}

__global__ void prep_copy_k(const float* __restrict__ I, const float* __restrict__ DL,
                            const float* __restrict__ ML, const float* __restrict__ E,
                            float* __restrict__ xin)
{
    int idx = blockIdx.x*blockDim.x + threadIdx.x;
    if (idx >= BB*HW1) return;
    int b = idx / HW1, p = idx - b*HW1;
    #pragma unroll
    for (int ch = 0; ch < 3; ++ch)
        xin[(size_t)(b*6+ch)*HW1 + p] = I[(size_t)(b*3+ch)*HW1 + p];
    xin[(size_t)(b*6+3)*HW1 + p] = DL[(size_t)b*HW1 + p];
    xin[(size_t)(b*6+4)*HW1 + p] = (ML[(size_t)b*HW1 + p] > 0.f) ? 1.f : 0.f;
    xin[(size_t)(b*6+5)*HW1 + p] = fminf(fmaxf(E[(size_t)b*HW1 + p], 0.f), 1.f);
}

// ============================================================================
__global__ void blend_k(const float* __restrict__ xin, const float* __restrict__ Dprev,
                        float* __restrict__ D, int Hs, int Ws)
{
    int HWs = Hs*Ws;
    int idx = blockIdx.x*blockDim.x + threadIdx.x;
    if (idx >= BB*HWs) return;
    int b = idx / HWs, p = idx - b*HWs;
    int y = p / Ws,    x = p - y*Ws;

    const float* Ep = xin + (size_t)(b*6+5)*HWs;
    float e  = Ep[p];
    float gx = (x > 0) ? e - Ep[p-1]  : 0.f;
    float gy = (y > 0) ? e - Ep[p-Ws] : 0.f;
    float g  = fminf((fabsf(gx) + fabsf(gy))*0.5f, 1.f);
    float wgt = 0.7f * fminf(fmaxf(1.f - g*10.0f, 0.f), 1.f);

    int Hp = Hs >> 1, Wp = Ws >> 1;
    float cy = 0.5f*(float)y - 0.25f;
    int  jy0 = (int)floorf(cy); float fy = cy - (float)jy0;
    int  ya = max(jy0, 0), yb = min(jy0+1, Hp-1);
    float cx = 0.5f*(float)x - 0.25f;
    int  jx0 = (int)floorf(cx); float fx = cx - (float)jx0;
    int  xa = max(jx0, 0), xb = min(jx0+1, Wp-1);

    const float* Dp = Dprev + (size_t)b*Hp*Wp;
    float up = (1.f-fy)*((1.f-fx)*Dp[ya*Wp+xa] + fx*Dp[ya*Wp+xb])
             +       fy*((1.f-fx)*Dp[yb*Wp+xa] + fx*Dp[yb*Wp+xb]);
    float P = fminf(fmaxf(e*10.f, 0.f), 10.f);
    D[(size_t)b*HWs + p] = wgt*up + (1.f - wgt)*P;
}

// ============================================================================
// 3x3 SAME conv, fp32, f32x2-packed FMA. 64x32 output tile, 8 couts/block.
// Per thread: 8 couts x (2 packed cols) x 4 rows.
// All weights for the cout-group preloaded to smem once; input tile
// double-buffered with register staging (one barrier per input channel).
// Grid: x = cout-group (fastest -> L2 reuse of input tile), y = tile, z = batch.
// ============================================================================
template<int CIN, bool RELU>
__global__ __launch_bounds__(256, 2)
void conv3x3_k(const float* __restrict__ in, const float* __restrict__ wgt,
               const float* __restrict__ bias, float* __restrict__ out,
               int H, int W, int coutTotal, int wCinStride, int tilesX)
{
    __shared__ __align__(16) float s_in[2][34][66];
    __shared__ float s_w[CIN*72];

    const int cg = blockIdx.x;
    const int x0 = (blockIdx.y % tilesX) * 64;
    const int y0 = (blockIdx.y / tilesX) * 32;
    const int b  = blockIdx.z;
    const int HWl = H*W;

    // preload all weights for this block's 8 couts
    for (int i = threadIdx.x; i < CIN*72; i += 256) {
        int ci = i / 72, r = i - ci*72;
        int co = r / 9,  t = r - co*9;
        int cout = cg*8 + co;
        s_w[i] = (cout < coutTotal) ? wgt[((size_t)cout*wCinStride + ci)*9 + t] : 0.f;
    }

    const int tx  = threadIdx.x & 31;       // column pair index
    const int wy4 = (threadIdx.x >> 5)*4;   // row base 0..28

    ull acc[8][4];
    #pragma unroll
    for (int co = 0; co < 8; ++co)
        #pragma unroll
        for (int r = 0; r < 4; ++r) acc[co][r] = 0ull;

    const float* inB = in + (size_t)b * CIN * HWl;

    // prologue: tile for ci=0
    {
        const float* inC = inB;
        for (int i = threadIdx.x; i < 34*66; i += 256) {
            int yy = i / 66, xx = i - yy*66;
            int gy = y0 + yy - 1, gx = x0 + xx - 1;
            float v = 0.f;
            if ((unsigned)gy < (unsigned)H && (unsigned)gx < (unsigned)W)
                v = inC[gy*W + gx];
            s_in[0][yy][xx] = v;
        }
    }
    __syncthreads();

    for (int ci = 0; ci < CIN; ++ci) {
        const int cur = ci & 1;

        // stage next channel's tile into registers (overlaps with compute)
        float stage[9];
        if (ci + 1 < CIN) {
            const float* inC = inB + (size_t)(ci+1)*HWl;
            #pragma unroll
            for (int k = 0; k < 9; ++k) {
                int i = threadIdx.x + k*256;
                float v = 0.f;
                if (i < 34*66) {
                    int yy = i / 66, xx = i - yy*66;
                    int gy = y0 + yy - 1, gx = x0 + xx - 1;
                    if ((unsigned)gy < (unsigned)H && (unsigned)gx < (unsigned)W)
                        v = inC[gy*W + gx];
                }
                stage[k] = v;
            }
        }

        const float* wci = s_w + ci*72;
        #pragma unroll
        for (int ky = 0; ky < 3; ++ky) {
            // packed neighbor pairs for the 4 output rows at this ky
            ull P[4][3];
            #pragma unroll
            for (int r = 0; r < 4; ++r) {
                const float* row = &s_in[cur][wy4 + ky + r][2*tx];
                float2 u01 = *(const float2*)(row);       // smem cols 2tx, 2tx+1
                float2 u23 = *(const float2*)(row + 2);   // smem cols 2tx+2, 2tx+3
                P[r][0] = pack2(u01.x, u01.y);
                P[r][1] = pack2(u01.y, u23.x);
                P[r][2] = pack2(u23.x, u23.y);
            }
            #pragma unroll
            for (int kx = 0; kx < 3; ++kx) {
                #pragma unroll
                for (int co = 0; co < 8; ++co) {
                    float w = wci[co*9 + ky*3 + kx];
                    ull wd = pack2(w, w);
                    #pragma unroll
                    for (int r = 0; r < 4; ++r)
                        fma2(acc[co][r], wd, P[r][kx]);
                }
            }
        }

        if (ci + 1 < CIN) {
            const int nxt = cur ^ 1;
            #pragma unroll
            for (int k = 0; k < 9; ++k) {
                int i = threadIdx.x + k*256;
                if (i < 34*66) {
                    int yy = i / 66, xx = i - yy*66;
                    s_in[nxt][yy][xx] = stage[k];
                }
            }
        }
        __syncthreads();
    }

    // epilogue: bias (+relu) and store; W even and x0+2tx even -> float2 store
    #pragma unroll
    for (int co = 0; co < 8; ++co) {
        int cout = cg*8 + co;
        if (cout >= coutTotal) break;
        float bb = bias[cout];
        float* outC = out + ((size_t)b*coutTotal + cout)*HWl;
        int gx = x0 + 2*tx;
        if (gx >= W) continue;
        #pragma unroll
        for (int r = 0; r < 4; ++r) {
            int gy = y0 + wy4 + r;
            if (gy >= H) continue;
            float2 v = unpack2(acc[co][r]);
            v.x += bb; v.y += bb;
            if (RELU) { v.x = fmaxf(v.x, 0.f); v.y = fmaxf(v.y, 0.f); }
            *(float2*)(outC + (size_t)gy*W + gx) = v;
        }
    }
}

// ============================================================================
// Post-process heads -> fused step-invariant propagation coefficients.
// ============================================================================
__global__ void postproc_k(const float* __restrict__ aff, const float* __restrict__ gate,
                           const float* __restrict__ curvp, const float* __restrict__ cw,
                           const float* __restrict__ xin, const float* __restrict__ D,
                           float* __restrict__ coef, int Hs, int Ws)
{
    int HWs = Hs*Ws;
    int idx = blockIdx.x*blockDim.x + threadIdx.x;
    if (idx >= BB*HWs) return;
    int b = idx / HWs, p = idx - b*HWs;
    int y = p / Ws,    x = p - y*Ws;

    float An[24];
    #pragma unroll
    for (int k = 0; k < 3; ++k) {
        float s1 = 0.f;
        #pragma unroll
        for (int j = 0; j < 8; ++j) {
            float v = aff[(size_t)(b*24 + k*8 + j)*HWs + p];
            An[k*8+j] = v;
            s1 += fabsf(v);
        }
        float inv = 1.0f/(s1 + 1e-6f);
        #pragma unroll
        for (int j = 0; j < 8; ++j) An[k*8+j] *= inv;
    }

    float g0 = gate[(size_t)(b*3+0)*HWs + p];
    float g1 = gate[(size_t)(b*3+1)*HWs + p];
    float g2 = gate[(size_t)(b*3+2)*HWs + p];
    float mx = fmaxf(g0, fmaxf(g1, g2));
    float e0 = expf(g0-mx), e1 = expf(g1-mx), e2 = expf(g2-mx);
    float einv = 1.0f/(e0+e1+e2);
    float sig[3] = {e0*einv, e1*einv, e2*einv};

    const float* Db = D + (size_t)b*HWs;
    float sk[3];
    #pragma unroll
    for (int k = 0; k < 3; ++k) {
        float cr = curvp[(size_t)(b*3+k)*HWs + p];
        #pragma unroll
        for (int ky = 0; ky < 3; ++ky) {
            int yy = y + ky - 1;
            if (yy < 0 || yy >= Hs) continue;
            #pragma unroll
            for (int kx = 0; kx < 3; ++kx) {
                int xx = x + kx - 1;
                if (xx < 0 || xx >= Ws) continue;
                cr += cw[(size_t)(k*65 + 64)*9 + ky*3 + kx] * (Db[yy*Ws + xx]*0.1f);
            }
        }
        float kap = 0.1f + 0.9f/(1.0f + expf(-cr));
        sk[k] = sig[k]*kap;
    }

    float mls = xin[(size_t)(b*6+4)*HWs + p];
    float dls = xin[(size_t)(b*6+3)*HWs + p];
    float m   = 0.9f*mls;
    float one = 1.0f - m;
    float Wsum = 0.f;
    #pragma unroll
    for (int k = 0; k < 3; ++k)
        #pragma unroll
        for (int j = 0; j < 8; ++j) {
            float Wv = sk[k]*An[k*8+j];
            Wsum += Wv;
            coef[(size_t)(b*26 + 1 + k*8 + j)*HWs + p] = one*Wv;
        }
    coef[(size_t)(b*26)*HWs + p]      = one*(1.0f - Wsum);
    coef[(size_t)(b*26 + 25)*HWs + p] = m*dls;
}

// ============================================================================
// One propagation step: 25-tap stencil with precomputed coefficients.
// ============================================================================
__global__ void prop_k(const float* __restrict__ Din, const float* __restrict__ coef,
                       float* __restrict__ Dout, int Hs, int Ws)
{
    __shared__ float sD[24][40];
    const int b  = blockIdx.z;
    const int x0 = blockIdx.x*32, y0 = blockIdx.y*16;
    const int HWs = Hs*Ws;
    const float* Db = Din + (size_t)b*HWs;

    int tid = threadIdx.y*32 + threadIdx.x;
    for (int i = tid; i < 24*40; i += 512) {
        int yy = i / 40, xx = i - yy*40;
        int gy = y0 + yy - 4, gx = x0 + xx - 4;
        sD[yy][xx] = ((unsigned)gy < (unsigned)Hs && (unsigned)gx < (unsigned)Ws)
                   ? Db[gy*Ws + gx] : 0.f;
    }
    __syncthreads();

    int x = x0 + threadIdx.x, y = y0 + threadIdx.y;
    if (x >= Ws || y >= Hs) return;
    int p = y*Ws + x;
    const float* cf = coef + (size_t)b*26*HWs;

    const int dyo[8] = {-1,-1,-1, 0, 0, 1, 1, 1};
    const int dxo[8] = {-1, 0, 1,-1, 1,-1, 0, 1};

    float acc = cf[p] * sD[threadIdx.y+4][threadIdx.x+4];
    #pragma unroll
    for (int k = 0; k < 3; ++k) {
        int d = 1 << k;
        #pragma unroll
        for (int j = 0; j < 8; ++j) {
            acc = fmaf(cf[(size_t)(1 + k*8 + j)*HWs + p],
                       sD[threadIdx.y + 4 + dyo[j]*d][threadIdx.x + 4 + dxo[j]*d],
                       acc);
        }
    }
    Dout[(size_t)b*HWs + p] = acc + cf[(size_t)25*HWs + p];
}

// ============================================================================
extern "C" void kernel_launch(void* const* d_in, const int* in_sizes, int n_in,
                              void* d_out, int out_size)
{
    const float* I   = (const float*)d_in[0];
    const float* DL  = (const float*)d_in[1];
    const float* ML  = (const float*)d_in[2];
    const float* E   = (const float*)d_in[3];
    const float* ew0 = (const float*)d_in[4];
    const float* eb0 = (const float*)d_in[5];
    const float* ew1 = (const float*)d_in[6];
    const float* eb1 = (const float*)d_in[7];
    const float* ew2 = (const float*)d_in[8];
    const float* eb2 = (const float*)d_in[9];
    const float* aw  = (const float*)d_in[10];
    const float* ab  = (const float*)d_in[11];
    const float* gw  = (const float*)d_in[12];
    const float* gb  = (const float*)d_in[13];
    const float* cw  = (const float*)d_in[14];
    const float* cbp = (const float*)d_in[15];

    float *xin, *f0, *f1, *aff, *gate, *curv, *coef, *Db, *D2, *Dp;
    cudaGetSymbolAddress((void**)&xin,  g_xin);
    cudaGetSymbolAddress((void**)&f0,   g_f0);
    cudaGetSymbolAddress((void**)&f1,   g_f1);
    cudaGetSymbolAddress((void**)&aff,  g_aff);
    cudaGetSymbolAddress((void**)&gate, g_gate);
    cudaGetSymbolAddress((void**)&curv, g_curv);
    cudaGetSymbolAddress((void**)&coef, g_coef);
    cudaGetSymbolAddress((void**)&Db,   g_D);
    cudaGetSymbolAddress((void**)&D2,   g_D2);
    cudaGetSymbolAddress((void**)&Dp,   g_Dp);

    const int scales[3] = {4, 2, 1};
    for (int si = 0; si < 3; ++si) {
        int s = scales[si];
        int Hs = HH / s, Ws = WW / s, HWs = Hs*Ws;
        int n = BB*HWs;
        int tpb = 256, nb = (n + tpb - 1)/tpb;

        if (si > 0) {
            int sp = scales[si-1];
            cudaMemcpyAsync(Dp, Db, sizeof(float)*(size_t)BB*(HH/sp)*(WW/sp),
                            cudaMemcpyDeviceToDevice);
        }

        if (s == 4)      prep_scale_k<4><<<nb, tpb>>>(I, DL, ML, E, xin, Db, Hs, Ws, 1);
        else if (s == 2) prep_scale_k<2><<<nb, tpb>>>(I, DL, ML, E, xin, Db, Hs, Ws, 0);
        else             prep_copy_k<<<nb, tpb>>>(I, DL, ML, E, xin);

        if (si > 0) blend_k<<<nb, tpb>>>(xin, Dp, Db, Hs, Ws);

        int tilesX = (Ws + 63)/64, tilesY = (Hs + 31)/32;
        dim3 blk(256);
        dim3 cgMain(8, tilesX*tilesY, BB);   // cout-group fastest -> input tile L2 reuse
        conv3x3_k<6,  true ><<<cgMain, blk>>>(xin, ew0, eb0, f0, Hs, Ws, 64, 6,  tilesX);
        conv3x3_k<64, true ><<<cgMain, blk>>>(f0,  ew1, eb1, f1, Hs, Ws, 64, 64, tilesX);
        conv3x3_k<64, true ><<<cgMain, blk>>>(f1,  ew2, eb2, f0, Hs, Ws, 64, 64, tilesX);
        dim3 cgAff(3, tilesX*tilesY, BB);
        conv3x3_k<64, false><<<cgAff,  blk>>>(f0, aw, ab, aff,  Hs, Ws, 24, 64, tilesX);
        dim3 cgHead(1, tilesX*tilesY, BB);
        conv3x3_k<64, false><<<cgHead, blk>>>(f0, gw, gb, gate, Hs, Ws, 3, 64, tilesX);
        // curv head: convolve ONLY the 64 feature channels; weight row stride is 65
        // (the 65th input channel D/10 is added analytically in postproc_k)
        conv3x3_k<64, false><<<cgHead, blk>>>(f0, cw, cbp, curv, Hs, Ws, 3, 65, tilesX);

        postproc_k<<<nb, tpb>>>(aff, gate, curv, cw, xin, Db, coef, Hs, Ws);

        dim3 pb(32, 16);
        dim3 pg((Ws+31)/32, (Hs+15)/16, BB);
        for (int t = 0; t < 6; ++t) {
            const float* src = (t & 1) ? D2 : Db;
            float*       dst = (t & 1) ? Db : D2;
            prop_k<<<pg, pb>>>(src, coef, dst, Hs, Ws);
        }
    }

    cudaMemcpyAsync(d_out, Db, sizeof(float)*(size_t)BB*HW1, cudaMemcpyDeviceToDevice);
}

// round 6
// speedup vs baseline: 1.3276x; 1.1556x over previous
#include <cuda_runtime.h>
#include <math.h>

// Problem constants (fixed by the dataset)
#define BB  2
#define HH  480
#define WW  640
#define HW1 (HH*WW)

typedef unsigned long long ull;

__device__ __forceinline__ void fma2(ull& d, ull a, ull b){
    asm("fma.rn.f32x2 %0, %1, %2, %0;" : "+l"(d) : "l"(a), "l"(b));
}
__device__ __forceinline__ ull pack2(float lo, float hi){
    ull r; asm("mov.b64 %0, {%1, %2};" : "=l"(r) : "f"(lo), "f"(hi)); return r;
}
__device__ __forceinline__ float2 unpack2(ull v){
    float2 r; asm("mov.b64 {%0, %1}, %2;" : "=f"(r.x), "=f"(r.y) : "l"(v)); return r;
}

// ---------------- scratch (static device memory; no allocations) ----------------
__device__ float g_xin  [BB*6 *HW1];
__device__ float g_f0   [BB*64*HW1];
__device__ float g_f1   [BB*64*HW1];
__device__ float g_heads[BB*30*HW1];   // 0-23 aff, 24-26 gate, 27-29 curv
__device__ float g_coef [BB*26*HW1];
__device__ float g_D    [BB*HW1];
__device__ float g_D2   [BB*HW1];
__device__ float g_Dp   [BB*HW1];

#define TILE_ELEMS 2244          // 34*66

// ============================================================================
// prep for s in {4,2}: antialiased triangle resize of I,E + valid-mean pool
// ============================================================================
template<int R>
__global__ void prep_scale_k(const float* __restrict__ I, const float* __restrict__ DL,
                             const float* __restrict__ ML, const float* __restrict__ E,
                             float* __restrict__ xin, float* __restrict__ Dout,
                             int Hs, int Ws, int writeD)
{
    int HWs = Hs*Ws;
    int idx = blockIdx.x*blockDim.x + threadIdx.x;
    if (idx >= BB*HWs) return;
    int b = idx / HWs, p = idx - b*HWs;
    int y = p / Ws,    x = p - y*Ws;

    float wy[2*R], wx[2*R];
    int   jy[2*R], jx[2*R];
    {
        float c = (y + 0.5f)*(float)R - 0.5f;
        int j0 = (int)ceilf(c - (float)R);
        float s = 0.f;
        #pragma unroll
        for (int t = 0; t < 2*R; ++t) {
            int j = j0 + t;
            float wt = 1.0f - fabsf((float)j - c)*(1.0f/(float)R);
            if (j < 0 || j >= HH || wt < 0.f) wt = 0.f;
            wy[t] = wt; s += wt;
            jy[t] = min(max(j,0), HH-1);
        }
        float inv = 1.0f/s;
        #pragma unroll
        for (int t = 0; t < 2*R; ++t) wy[t] *= inv;
    }
    {
        float c = (x + 0.5f)*(float)R - 0.5f;
        int j0 = (int)ceilf(c - (float)R);
        float s = 0.f;
        #pragma unroll
        for (int t = 0; t < 2*R; ++t) {
            int j = j0 + t;
            float wt = 1.0f - fabsf((float)j - c)*(1.0f/(float)R);
            if (j < 0 || j >= WW || wt < 0.f) wt = 0.f;
            wx[t] = wt; s += wt;
            jx[t] = min(max(j,0), WW-1);
        }
        float inv = 1.0f/s;
        #pragma unroll
        for (int t = 0; t < 2*R; ++t) wx[t] *= inv;
    }

    #pragma unroll
    for (int ch = 0; ch < 3; ++ch) {
        const float* src = I + (size_t)(b*3+ch)*HW1;
        float a = 0.f;
        #pragma unroll
        for (int ty = 0; ty < 2*R; ++ty) {
            if (wy[ty] == 0.f) continue;
            const float* row = src + jy[ty]*WW;
            float rs = 0.f;
            #pragma unroll
            for (int t = 0; t < 2*R; ++t) rs += wx[t]*row[jx[t]];
            a += wy[ty]*rs;
        }
        xin[(size_t)(b*6+ch)*HWs + p] = a;
    }
    {
        const float* src = E + (size_t)b*HW1;
        float a = 0.f;
        #pragma unroll
        for (int ty = 0; ty < 2*R; ++ty) {
            if (wy[ty] == 0.f) continue;
            const float* row = src + jy[ty]*WW;
            float rs = 0.f;
            #pragma unroll
            for (int t = 0; t < 2*R; ++t) rs += wx[t]*row[jx[t]];
            a += wy[ty]*rs;
        }
        a = fminf(fmaxf(a, 0.f), 1.f);
        xin[(size_t)(b*6+5)*HWs + p] = a;
        if (writeD) Dout[(size_t)b*HWs + p] = fminf(fmaxf(a*10.f, 0.f), 10.f);
    }
    {
        const float* dlb = DL + (size_t)b*HW1;
        const float* mlb = ML + (size_t)b*HW1;
        float ssum = 0.f, cnt = 0.f;
        #pragma unroll
        for (int iy = 0; iy < R; ++iy) {
            int gy = y*R + iy;
            #pragma unroll
            for (int ix = 0; ix < R; ++ix) {
                int gi = gy*WW + x*R + ix;
                float m = (mlb[gi] > 0.f) ? 1.f : 0.f;
                cnt  += m;
                ssum += dlb[gi]*m;
            }
        }
        float mls = (cnt > 0.f) ? 1.f : 0.f;
        float dls = (cnt > 0.f) ? ssum/(cnt + 1e-6f) : 0.f;
        xin[(size_t)(b*6+3)*HWs + p] = dls;
        xin[(size_t)(b*6+4)*HWs + p] = mls;
    }
}

__global__ void prep_copy_k(const float* __restrict__ I, const float* __restrict__ DL,
                            const float* __restrict__ ML, const float* __restrict__ E,
                            float* __restrict__ xin)
{
    int idx = blockIdx.x*blockDim.x + threadIdx.x;
    if (idx >= BB*HW1) return;
    int b = idx / HW1, p = idx - b*HW1;
    #pragma unroll
    for (int ch = 0; ch < 3; ++ch)
        xin[(size_t)(b*6+ch)*HW1 + p] = I[(size_t)(b*3+ch)*HW1 + p];
    xin[(size_t)(b*6+3)*HW1 + p] = DL[(size_t)b*HW1 + p];
    xin[(size_t)(b*6+4)*HW1 + p] = (ML[(size_t)b*HW1 + p] > 0.f) ? 1.f : 0.f;
    xin[(size_t)(b*6+5)*HW1 + p] = fminf(fmaxf(E[(size_t)b*HW1 + p], 0.f), 1.f);
}

// ============================================================================
__global__ void blend_k(const float* __restrict__ xin, const float* __restrict__ Dprev,
                        float* __restrict__ D, int Hs, int Ws)
{
    int HWs = Hs*Ws;
    int idx = blockIdx.x*blockDim.x + threadIdx.x;
    if (idx >= BB*HWs) return;
    int b = idx / HWs, p = idx - b*HWs;
    int y = p / Ws,    x = p - y*Ws;

    const float* Ep = xin + (size_t)(b*6+5)*HWs;
    float e  = Ep[p];
    float gx = (x > 0) ? e - Ep[p-1]  : 0.f;
    float gy = (y > 0) ? e - Ep[p-Ws] : 0.f;
    float g  = fminf((fabsf(gx) + fabsf(gy))*0.5f, 1.f);
    float wgt = 0.7f * fminf(fmaxf(1.f - g*10.0f, 0.f), 1.f);

    int Hp = Hs >> 1, Wp = Ws >> 1;
    float cy = 0.5f*(float)y - 0.25f;
    int  jy0 = (int)floorf(cy); float fy = cy - (float)jy0;
    int  ya = max(jy0, 0), yb = min(jy0+1, Hp-1);
    float cx = 0.5f*(float)x - 0.25f;
    int  jx0 = (int)floorf(cx); float fx = cx - (float)jx0;
    int  xa = max(jx0, 0), xb = min(jx0+1, Wp-1);

    const float* Dp = Dprev + (size_t)b*Hp*Wp;
    float up = (1.f-fy)*((1.f-fx)*Dp[ya*Wp+xa] + fx*Dp[ya*Wp+xb])
             +       fy*((1.f-fx)*Dp[yb*Wp+xa] + fx*Dp[yb*Wp+xb]);
    float P = fminf(fmaxf(e*10.f, 0.f), 10.f);
    D[(size_t)b*HWs + p] = wgt*up + (1.f - wgt)*P;
}

// ============================================================================
// Weight getters (global memory layout differs per conv)
// ============================================================================
struct WStd {
    const float* w; int stride; int coutTotal;
    __device__ __forceinline__ float get(int cout, int ci, int t) const {
        return (cout < coutTotal) ? w[((size_t)cout*stride + ci)*9 + t] : 0.f;
    }
};
struct WHeads {
    const float* aw; const float* gw; const float* cwp;
    __device__ __forceinline__ float get(int c, int ci, int t) const {
        if (c < 24) return aw[((size_t)c*64       + ci)*9 + t];
        if (c < 27) return gw[((size_t)(c-24)*64  + ci)*9 + t];
        if (c < 30) return cwp[((size_t)(c-27)*65 + ci)*9 + t];
        return 0.f;
    }
};

// ============================================================================
// conv core: 64x32 output tile, 8 couts/block, f32x2 FMA.
// - input: register-staged double buffer in smem (R3-proven pattern)
// - weights: packed (w,w) ull in smem, loaded in HALF-channel chunks
// - 6-row P reuse
// biasLocal is indexed by co (0..7); caller pre-offsets.
// ============================================================================
template<int CIN, bool RELU, typename WG>
__device__ __forceinline__
void conv_core(const float* __restrict__ inB, WG wgf,
               const float* __restrict__ biasLocal,
               float* __restrict__ outBase,
               int H, int W, int x0, int y0, int coutTotal, int cg,
               float* __restrict__ s_in, ull* __restrict__ s_w)
{
    constexpr int HALF = (CIN > 32) ? 32 : CIN;
    const int HWl = H*W;
    const int tid = threadIdx.x;

    // weights for half 0 (channels 0..HALF-1)
    for (int i = tid; i < HALF*72; i += 256) {
        int cl = i / 72, r = i - cl*72;
        int co = r / 9,  t = r - co*9;
        float w = wgf.get(cg*8 + co, cl, t);
        s_w[i] = pack2(w, w);
    }

    // per-thread tile-load geometry (9 slots)
    int off[9]; unsigned pmask = 0;
    #pragma unroll
    for (int k = 0; k < 9; ++k) {
        int i = tid + k*256;
        int yy = i/66, xx = i - yy*66;
        int gy = y0+yy-1, gx = x0+xx-1;
        bool ok = (i < TILE_ELEMS) && ((unsigned)gy < (unsigned)H) && ((unsigned)gx < (unsigned)W);
        off[k] = ok ? gy*W+gx : 0;
        if (ok) pmask |= (1u<<k);
    }

    // prologue: tile for ci=0
    #pragma unroll
    for (int k = 0; k < 9; ++k) {
        int i = tid + k*256;
        if (k < 8 || i < TILE_ELEMS)
            s_in[i] = (pmask>>k & 1) ? inB[off[k]] : 0.f;
    }
    __syncthreads();   // covers both s_in[0] and the half-0 weights

    const int tx  = tid & 31;
    const int wy4 = (tid >> 5)*4;

    ull acc[8][4];
    #pragma unroll
    for (int co = 0; co < 8; ++co)
        #pragma unroll
        for (int r = 0; r < 4; ++r) acc[co][r] = 0ull;

    for (int ci = 0; ci < CIN; ++ci) {
        const int cur = ci & 1;

        // stage next channel into registers (overlaps with compute)
        float stage[9];
        if (ci + 1 < CIN) {
            const float* src = inB + (size_t)(ci+1)*HWl;
            #pragma unroll
            for (int k = 0; k < 9; ++k) {
                int i = tid + k*256;
                float v = 0.f;
                if ((k < 8 || i < TILE_ELEMS) && (pmask>>k & 1)) v = src[off[k]];
                stage[k] = v;
            }
        }

        const float* buf = s_in + cur*TILE_ELEMS;

        // packed neighbor pairs for the 6 rows this warp needs
        ull P[6][3];
        #pragma unroll
        for (int rr = 0; rr < 6; ++rr) {
            const float* row = buf + (wy4 + rr)*66 + 2*tx;
            float2 u01 = *(const float2*)(row);
            float2 u23 = *(const float2*)(row + 2);
            P[rr][0] = pack2(u01.x, u01.y);
            P[rr][1] = pack2(u01.y, u23.x);
            P[rr][2] = pack2(u23.x, u23.y);
        }

        const ull* wci = s_w + (ci % HALF)*72;
        #pragma unroll
        for (int co = 0; co < 8; ++co) {
            #pragma unroll
            for (int ky = 0; ky < 3; ++ky)
                #pragma unroll
                for (int kx = 0; kx < 3; ++kx) {
                    ull wd = wci[co*9 + ky*3 + kx];
                    fma2(acc[co][0], wd, P[ky+0][kx]);
                    fma2(acc[co][1], wd, P[ky+1][kx]);
                    fma2(acc[co][2], wd, P[ky+2][kx]);
                    fma2(acc[co][3], wd, P[ky+3][kx]);
                }
        }

        // write staged tile into the other buffer
        if (ci + 1 < CIN) {
            float* dst = s_in + (cur^1)*TILE_ELEMS;
            #pragma unroll
            for (int k = 0; k < 9; ++k) {
                int i = tid + k*256;
                if (k < 8 || i < TILE_ELEMS) dst[i] = stage[k];
            }
        }
        __syncthreads();

        // at a half boundary, reload weights for the next HALF channels
        if (HALF < CIN && (ci % HALF) == HALF-1 && ci + 1 < CIN) {
            for (int i = tid; i < HALF*72; i += 256) {
                int cl = i / 72, r = i - cl*72;
                int co = r / 9,  t = r - co*9;
                float w = wgf.get(cg*8 + co, ci + 1 + cl, t);
                s_w[i] = pack2(w, w);
            }
            __syncthreads();
        }
    }

    // epilogue: bias (+relu), float2 store (W even, x0+2tx even)
    #pragma unroll
    for (int co = 0; co < 8; ++co) {
        int cout = cg*8 + co;
        if (cout >= coutTotal) break;
        float bb = biasLocal[co];
        float* outC = outBase + (size_t)cout*HWl;
        int gx = x0 + 2*tx;
        if (gx >= W) continue;
        #pragma unroll
        for (int r = 0; r < 4; ++r) {
            int gy = y0 + wy4 + r;
            if (gy >= H) continue;
            float2 v = unpack2(acc[co][r]);
            v.x += bb; v.y += bb;
            if (RELU) { v.x = fmaxf(v.x, 0.f); v.y = fmaxf(v.y, 0.f); }
            *(float2*)(outC + (size_t)gy*W + gx) = v;
        }
    }
}

// standard conv
template<int CIN, bool RELU>
__global__ __launch_bounds__(256, 2)
void conv3x3_k(const float* __restrict__ in, const float* __restrict__ wgt,
               const float* __restrict__ bias, float* __restrict__ out,
               int H, int W, int coutTotal, int wCinStride, int tilesX)
{
    constexpr int HALF = (CIN > 32) ? 32 : CIN;
    __shared__ __align__(16) float s_in[2*TILE_ELEMS];
    __shared__ ull s_w[HALF*72];

    const int cg = blockIdx.x;
    const int x0 = (blockIdx.y % tilesX) * 64;
    const int y0 = (blockIdx.y / tilesX) * 32;
    const int b  = blockIdx.z;

    WStd wg{wgt, wCinStride, coutTotal};
    conv_core<CIN, RELU>(in + (size_t)b*CIN*H*W, wg, bias + cg*8,
                         out + (size_t)b*coutTotal*H*W,
                         H, W, x0, y0, coutTotal, cg, s_in, s_w);
}

// fused heads conv: 30 couts (aff 24, gate 3, curv 3) in one pass
__global__ __launch_bounds__(256, 2)
void convheads_k(const float* __restrict__ in,
                 const float* __restrict__ aw, const float* __restrict__ ab,
                 const float* __restrict__ gw, const float* __restrict__ gb,
                 const float* __restrict__ cw, const float* __restrict__ cb,
                 float* __restrict__ out, int H, int W, int tilesX)
{
    __shared__ __align__(16) float s_in[2*TILE_ELEMS];
    __shared__ ull s_w[32*72];
    __shared__ float s_bias[8];

    const int cg = blockIdx.x;           // 0..3
    const int x0 = (blockIdx.y % tilesX) * 64;
    const int y0 = (blockIdx.y / tilesX) * 32;
    const int b  = blockIdx.z;

    if (threadIdx.x < 8) {
        int c = cg*8 + (int)threadIdx.x;
        float bv = 0.f;
        if (c < 24)      bv = ab[c];
        else if (c < 27) bv = gb[c-24];
        else if (c < 30) bv = cb[c-27];
        s_bias[threadIdx.x] = bv;
    }
    // s_bias is read only in the epilogue, after many __syncthreads

    WHeads wg{aw, gw, cw};
    conv_core<64, false>(in + (size_t)b*64*H*W, wg, s_bias,
                         out + (size_t)b*30*H*W,
                         H, W, x0, y0, 30, cg, s_in, s_w);
}

// ============================================================================
// Post-process heads -> fused step-invariant propagation coefficients.
// heads layout: planes 0-23 aff, 24-26 gate, 27-29 curv (64-ch part only)
// ============================================================================
__global__ void postproc_k(const float* __restrict__ heads, const float* __restrict__ cw,
                           const float* __restrict__ xin, const float* __restrict__ D,
                           float* __restrict__ coef, int Hs, int Ws)
{
    int HWs = Hs*Ws;
    int idx = blockIdx.x*blockDim.x + threadIdx.x;
    if (idx >= BB*HWs) return;
    int b = idx / HWs, p = idx - b*HWs;
    int y = p / Ws,    x = p - y*Ws;

    float An[24];
    #pragma unroll
    for (int k = 0; k < 3; ++k) {
        float s1 = 0.f;
        #pragma unroll
        for (int j = 0; j < 8; ++j) {
            float v = heads[(size_t)(b*30 + k*8 + j)*HWs + p];
            An[k*8+j] = v;
            s1 += fabsf(v);
        }
        float inv = 1.0f/(s1 + 1e-6f);
        #pragma unroll
        for (int j = 0; j < 8; ++j) An[k*8+j] *= inv;
    }

    float g0 = heads[(size_t)(b*30+24)*HWs + p];
    float g1 = heads[(size_t)(b*30+25)*HWs + p];
    float g2 = heads[(size_t)(b*30+26)*HWs + p];
    float mx = fmaxf(g0, fmaxf(g1, g2));
    float e0 = expf(g0-mx), e1 = expf(g1-mx), e2 = expf(g2-mx);
    float einv = 1.0f/(e0+e1+e2);
    float sig[3] = {e0*einv, e1*einv, e2*einv};

    const float* Db = D + (size_t)b*HWs;
    float sk[3];
    #pragma unroll
    for (int k = 0; k < 3; ++k) {
        float cr = heads[(size_t)(b*30+27+k)*HWs + p];
        #pragma unroll
        for (int ky = 0; ky < 3; ++ky) {
            int yy = y + ky - 1;
            if (yy < 0 || yy >= Hs) continue;
            #pragma unroll
            for (int kx = 0; kx < 3; ++kx) {
                int xx = x + kx - 1;
                if (xx < 0 || xx >= Ws) continue;
                cr += cw[(size_t)(k*65 + 64)*9 + ky*3 + kx] * (Db[yy*Ws + xx]*0.1f);
            }
        }
        float kap = 0.1f + 0.9f/(1.0f + expf(-cr));
        sk[k] = sig[k]*kap;
    }

    float mls = xin[(size_t)(b*6+4)*HWs + p];
    float dls = xin[(size_t)(b*6+3)*HWs + p];
    float m   = 0.9f*mls;
    float one = 1.0f - m;
    float Wsum = 0.f;
    #pragma unroll
    for (int k = 0; k < 3; ++k)
        #pragma unroll
        for (int j = 0; j < 8; ++j) {
            float Wv = sk[k]*An[k*8+j];
            Wsum += Wv;
            coef[(size_t)(b*26 + 1 + k*8 + j)*HWs + p] = one*Wv;
        }
    coef[(size_t)(b*26)*HWs + p]      = one*(1.0f - Wsum);
    coef[(size_t)(b*26 + 25)*HWs + p] = m*dls;
}

// ============================================================================
// One propagation step: 25-tap stencil with precomputed coefficients.
// ============================================================================
__global__ void prop_k(const float* __restrict__ Din, const float* __restrict__ coef,
                       float* __restrict__ Dout, int Hs, int Ws)
{
    __shared__ float sD[24][40];
    const int b  = blockIdx.z;
    const int x0 = blockIdx.x*32, y0 = blockIdx.y*16;
    const int HWs = Hs*Ws;
    const float* Db = Din + (size_t)b*HWs;

    int tid = threadIdx.y*32 + threadIdx.x;
    for (int i = tid; i < 24*40; i += 512) {
        int yy = i / 40, xx = i - yy*40;
        int gy = y0 + yy - 4, gx = x0 + xx - 4;
        sD[yy][xx] = ((unsigned)gy < (unsigned)Hs && (unsigned)gx < (unsigned)Ws)
                   ? Db[gy*Ws + gx] : 0.f;
    }
    __syncthreads();

    int x = x0 + threadIdx.x, y = y0 + threadIdx.y;
    if (x >= Ws || y >= Hs) return;
    int p = y*Ws + x;
    const float* cf = coef + (size_t)b*26*HWs;

    const int dyo[8] = {-1,-1,-1, 0, 0, 1, 1, 1};
    const int dxo[8] = {-1, 0, 1,-1, 1,-1, 0, 1};

    float acc = cf[p] * sD[threadIdx.y+4][threadIdx.x+4];
    #pragma unroll
    for (int k = 0; k < 3; ++k) {
        int d = 1 << k;
        #pragma unroll
        for (int j = 0; j < 8; ++j) {
            acc = fmaf(cf[(size_t)(1 + k*8 + j)*HWs + p],
                       sD[threadIdx.y + 4 + dyo[j]*d][threadIdx.x + 4 + dxo[j]*d],
                       acc);
        }
    }
    Dout[(size_t)b*HWs + p] = acc + cf[(size_t)25*HWs + p];
}

// ============================================================================
extern "C" void kernel_launch(void* const* d_in, const int* in_sizes, int n_in,
                              void* d_out, int out_size)
{
    const float* I   = (const float*)d_in[0];
    const float* DL  = (const float*)d_in[1];
    const float* ML  = (const float*)d_in[2];
    const float* E   = (const float*)d_in[3];
    const float* ew0 = (const float*)d_in[4];
    const float* eb0 = (const float*)d_in[5];
    const float* ew1 = (const float*)d_in[6];
    const float* eb1 = (const float*)d_in[7];
    const float* ew2 = (const float*)d_in[8];
    const float* eb2 = (const float*)d_in[9];
    const float* aw  = (const float*)d_in[10];
    const float* ab  = (const float*)d_in[11];
    const float* gw  = (const float*)d_in[12];
    const float* gb  = (const float*)d_in[13];
    const float* cw  = (const float*)d_in[14];
    const float* cbp = (const float*)d_in[15];

    float *xin, *f0, *f1, *heads, *coef, *Db, *D2, *Dp;
    cudaGetSymbolAddress((void**)&xin,   g_xin);
    cudaGetSymbolAddress((void**)&f0,    g_f0);
    cudaGetSymbolAddress((void**)&f1,    g_f1);
    cudaGetSymbolAddress((void**)&heads, g_heads);
    cudaGetSymbolAddress((void**)&coef,  g_coef);
    cudaGetSymbolAddress((void**)&Db,    g_D);
    cudaGetSymbolAddress((void**)&D2,    g_D2);
    cudaGetSymbolAddress((void**)&Dp,    g_Dp);

    const int scales[3] = {4, 2, 1};
    for (int si = 0; si < 3; ++si) {
        int s = scales[si];
        int Hs = HH / s, Ws = WW / s, HWs = Hs*Ws;
        int n = BB*HWs;
        int tpb = 256, nb = (n + tpb - 1)/tpb;

        if (si > 0) {
            int sp = scales[si-1];
            cudaMemcpyAsync(Dp, Db, sizeof(float)*(size_t)BB*(HH/sp)*(WW/sp),
                            cudaMemcpyDeviceToDevice);
        }

        if (s == 4)      prep_scale_k<4><<<nb, tpb>>>(I, DL, ML, E, xin, Db, Hs, Ws, 1);
        else if (s == 2) prep_scale_k<2><<<nb, tpb>>>(I, DL, ML, E, xin, Db, Hs, Ws, 0);
        else             prep_copy_k<<<nb, tpb>>>(I, DL, ML, E, xin);

        if (si > 0) blend_k<<<nb, tpb>>>(xin, Dp, Db, Hs, Ws);

        int tilesX = (Ws + 63)/64, tilesY = (Hs + 31)/32;
        dim3 blk(256);
        dim3 cgMain(8, tilesX*tilesY, BB);
        conv3x3_k<6,  true ><<<cgMain, blk>>>(xin, ew0, eb0, f0, Hs, Ws, 64, 6,  tilesX);
        conv3x3_k<64, true ><<<cgMain, blk>>>(f0,  ew1, eb1, f1, Hs, Ws, 64, 64, tilesX);
        conv3x3_k<64, true ><<<cgMain, blk>>>(f1,  ew2, eb2, f0, Hs, Ws, 64, 64, tilesX);
        dim3 cgHeads(4, tilesX*tilesY, BB);
        convheads_k<<<cgHeads, blk>>>(f0, aw, ab, gw, gb, cw, cbp,
                                      heads, Hs, Ws, tilesX);

        postproc_k<<<nb, tpb>>>(heads, cw, xin, Db, coef, Hs, Ws);

        dim3 pb(32, 16);
        dim3 pg((Ws+31)/32, (Hs+15)/16, BB);
        for (int t = 0; t < 6; ++t) {
            const float* src = (t & 1) ? D2 : Db;
            float*       dst = (t & 1) ? Db : D2;
            prop_k<<<pg, pb>>>(src, coef, dst, Hs, Ws);
        }
    }

    cudaMemcpyAsync(d_out, Db, sizeof(float)*(size_t)BB*HW1, cudaMemcpyDeviceToDevice);
}

// round 7
// speedup vs baseline: 1.3308x; 1.0024x over previous
#include <cuda_runtime.h>
#include <math.h>

// Problem constants (fixed by the dataset)
#define BB  2
#define HH  480
#define WW  640
#define HW1 (HH*WW)

typedef unsigned long long ull;

__device__ __forceinline__ void fma2(ull& d, ull a, ull b){
    asm("fma.rn.f32x2 %0, %1, %2, %0;" : "+l"(d) : "l"(a), "l"(b));
}
__device__ __forceinline__ ull pack2(float lo, float hi){
    ull r; asm("mov.b64 %0, {%1, %2};" : "=l"(r) : "f"(lo), "f"(hi)); return r;
}
__device__ __forceinline__ float2 unpack2(ull v){
    float2 r; asm("mov.b64 {%0, %1}, %2;" : "=f"(r.x), "=f"(r.y) : "l"(v)); return r;
}

// ---------------- scratch (static device memory; no allocations) ----------------
__device__ float g_xin  [BB*6 *HW1];
__device__ float g_f0   [BB*64*HW1];
__device__ float g_f1   [BB*64*HW1];
__device__ float g_heads[BB*30*HW1];   // 0-23 aff, 24-26 gate, 27-29 curv
__device__ float g_coef [BB*26*HW1];
__device__ float g_D    [BB*HW1];
__device__ float g_D2   [BB*HW1];
__device__ float g_Dp   [BB*HW1];

#define TILE_ELEMS 2244          // 34*66

// ============================================================================
// prep for s in {4,2}: antialiased triangle resize of I,E + valid-mean pool
// ============================================================================
template<int R>
__global__ void prep_scale_k(const float* __restrict__ I, const float* __restrict__ DL,
                             const float* __restrict__ ML, const float* __restrict__ E,
                             float* __restrict__ xin, float* __restrict__ Dout,
                             int Hs, int Ws, int writeD)
{
    int HWs = Hs*Ws;
    int idx = blockIdx.x*blockDim.x + threadIdx.x;
    if (idx >= BB*HWs) return;
    int b = idx / HWs, p = idx - b*HWs;
    int y = p / Ws,    x = p - y*Ws;

    float wy[2*R], wx[2*R];
    int   jy[2*R], jx[2*R];
    {
        float c = (y + 0.5f)*(float)R - 0.5f;
        int j0 = (int)ceilf(c - (float)R);
        float s = 0.f;
        #pragma unroll
        for (int t = 0; t < 2*R; ++t) {
            int j = j0 + t;
            float wt = 1.0f - fabsf((float)j - c)*(1.0f/(float)R);
            if (j < 0 || j >= HH || wt < 0.f) wt = 0.f;
            wy[t] = wt; s += wt;
            jy[t] = min(max(j,0), HH-1);
        }
        float inv = 1.0f/s;
        #pragma unroll
        for (int t = 0; t < 2*R; ++t) wy[t] *= inv;
    }
    {
        float c = (x + 0.5f)*(float)R - 0.5f;
        int j0 = (int)ceilf(c - (float)R);
        float s = 0.f;
        #pragma unroll
        for (int t = 0; t < 2*R; ++t) {
            int j = j0 + t;
            float wt = 1.0f - fabsf((float)j - c)*(1.0f/(float)R);
            if (j < 0 || j >= WW || wt < 0.f) wt = 0.f;
            wx[t] = wt; s += wt;
            jx[t] = min(max(j,0), WW-1);
        }
        float inv = 1.0f/s;
        #pragma unroll
        for (int t = 0; t < 2*R; ++t) wx[t] *= inv;
    }

    #pragma unroll
    for (int ch = 0; ch < 3; ++ch) {
        const float* src = I + (size_t)(b*3+ch)*HW1;
        float a = 0.f;
        #pragma unroll
        for (int ty = 0; ty < 2*R; ++ty) {
            if (wy[ty] == 0.f) continue;
            const float* row = src + jy[ty]*WW;
            float rs = 0.f;
            #pragma unroll
            for (int t = 0; t < 2*R; ++t) rs += wx[t]*row[jx[t]];
            a += wy[ty]*rs;
        }
        xin[(size_t)(b*6+ch)*HWs + p] = a;
    }
    {
        const float* src = E + (size_t)b*HW1;
        float a = 0.f;
        #pragma unroll
        for (int ty = 0; ty < 2*R; ++ty) {
            if (wy[ty] == 0.f) continue;
            const float* row = src + jy[ty]*WW;
            float rs = 0.f;
            #pragma unroll
            for (int t = 0; t < 2*R; ++t) rs += wx[t]*row[jx[t]];
            a += wy[ty]*rs;
        }
        a = fminf(fmaxf(a, 0.f), 1.f);
        xin[(size_t)(b*6+5)*HWs + p] = a;
        if (writeD) Dout[(size_t)b*HWs + p] = fminf(fmaxf(a*10.f, 0.f), 10.f);
    }
    {
        const float* dlb = DL + (size_t)b*HW1;
        const float* mlb = ML + (size_t)b*HW1;
        float ssum = 0.f, cnt = 0.f;
        #pragma unroll
        for (int iy = 0; iy < R; ++iy) {
            int gy = y*R + iy;
            #pragma unroll
            for (int ix = 0; ix < R; ++ix) {
                int gi = gy*WW + x*R + ix;
                float m = (mlb[gi] > 0.f) ? 1.f : 0.f;
                cnt  += m;
                ssum += dlb[gi]*m;
            }
        }
        float mls = (cnt > 0.f) ? 1.f : 0.f;
        float dls = (cnt > 0.f) ? ssum/(cnt + 1e-6f) : 0.f;
        xin[(size_t)(b*6+3)*HWs + p] = dls;
        xin[(size_t)(b*6+4)*HWs + p] = mls;
    }
}

__global__ void prep_copy_k(const float* __restrict__ I, const float* __restrict__ DL,
                            const float* __restrict__ ML, const float* __restrict__ E,
                            float* __restrict__ xin)
{
    int idx = blockIdx.x*blockDim.x + threadIdx.x;
    if (idx >= BB*HW1) return;
    int b = idx / HW1, p = idx - b*HW1;
    #pragma unroll
    for (int ch = 0; ch < 3; ++ch)
        xin[(size_t)(b*6+ch)*HW1 + p] = I[(size_t)(b*3+ch)*HW1 + p];
    xin[(size_t)(b*6+3)*HW1 + p] = DL[(size_t)b*HW1 + p];
    xin[(size_t)(b*6+4)*HW1 + p] = (ML[(size_t)b*HW1 + p] > 0.f) ? 1.f : 0.f;
    xin[(size_t)(b*6+5)*HW1 + p] = fminf(fmaxf(E[(size_t)b*HW1 + p], 0.f), 1.f);
}

// ============================================================================
__global__ void blend_k(const float* __restrict__ xin, const float* __restrict__ Dprev,
                        float* __restrict__ D, int Hs, int Ws)
{
    int HWs = Hs*Ws;
    int idx = blockIdx.x*blockDim.x + threadIdx.x;
    if (idx >= BB*HWs) return;
    int b = idx / HWs, p = idx - b*HWs;
    int y = p / Ws,    x = p - y*Ws;

    const float* Ep = xin + (size_t)(b*6+5)*HWs;
    float e  = Ep[p];
    float gx = (x > 0) ? e - Ep[p-1]  : 0.f;
    float gy = (y > 0) ? e - Ep[p-Ws] : 0.f;
    float g  = fminf((fabsf(gx) + fabsf(gy))*0.5f, 1.f);
    float wgt = 0.7f * fminf(fmaxf(1.f - g*10.0f, 0.f), 1.f);

    int Hp = Hs >> 1, Wp = Ws >> 1;
    float cy = 0.5f*(float)y - 0.25f;
    int  jy0 = (int)floorf(cy); float fy = cy - (float)jy0;
    int  ya = max(jy0, 0), yb = min(jy0+1, Hp-1);
    float cx = 0.5f*(float)x - 0.25f;
    int  jx0 = (int)floorf(cx); float fx = cx - (float)jx0;
    int  xa = max(jx0, 0), xb = min(jx0+1, Wp-1);

    const float* Dp = Dprev + (size_t)b*Hp*Wp;
    float up = (1.f-fy)*((1.f-fx)*Dp[ya*Wp+xa] + fx*Dp[ya*Wp+xb])
             +       fy*((1.f-fx)*Dp[yb*Wp+xa] + fx*Dp[yb*Wp+xb]);
    float P = fminf(fmaxf(e*10.f, 0.f), 10.f);
    D[(size_t)b*HWs + p] = wgt*up + (1.f - wgt)*P;
}

// ============================================================================
// Weight getters (global memory layout differs per conv)
// ============================================================================
struct WStd {
    const float* w; int stride; int coutTotal;
    __device__ __forceinline__ float get(int cout, int ci, int t) const {
        return (cout < coutTotal) ? w[((size_t)cout*stride + ci)*9 + t] : 0.f;
    }
};
struct WHeads {
    const float* aw; const float* gw; const float* cwp;
    __device__ __forceinline__ float get(int c, int ci, int t) const {
        if (c < 24) return aw[((size_t)c*64       + ci)*9 + t];
        if (c < 27) return gw[((size_t)(c-24)*64  + ci)*9 + t];
        if (c < 30) return cwp[((size_t)(c-27)*65 + ci)*9 + t];
        return 0.f;
    }
};

// ============================================================================
// conv core: 64x32 output tile, 8 couts/block, f32x2 FMA.
// - input: 3-buffer rotation; LDG for channel ci+2 issued at round ci,
//   stored (STS) at round ci+1, consumed at round ci+2 -> a full round of
//   latency slack, one barrier per round, no cp.async.
// - weights: packed (w,w) ull in smem, loaded in HALF-channel chunks
// - 6-row P reuse
// biasLocal is indexed by co (0..7); caller pre-offsets.
// ============================================================================
template<int CIN, bool RELU, typename WG>
__device__ __forceinline__
void conv_core(const float* __restrict__ inB, WG wgf,
               const float* __restrict__ biasLocal,
               float* __restrict__ outBase,
               int H, int W, int x0, int y0, int coutTotal, int cg,
               float* __restrict__ s_in, ull* __restrict__ s_w)
{
    constexpr int HALF = (CIN > 32) ? 32 : CIN;
    const int HWl = H*W;
    const int tid = threadIdx.x;

    // weights for half 0 (channels 0..HALF-1)
    for (int i = tid; i < HALF*72; i += 256) {
        int cl = i / 72, r = i - cl*72;
        int co = r / 9,  t = r - co*9;
        float w = wgf.get(cg*8 + co, cl, t);
        s_w[i] = pack2(w, w);
    }

    // per-thread tile-load geometry (9 slots)
    int off[9]; unsigned pmask = 0;
    #pragma unroll
    for (int k = 0; k < 9; ++k) {
        int i = tid + k*256;
        int yy = i/66, xx = i - yy*66;
        int gy = y0+yy-1, gx = x0+xx-1;
        bool ok = (i < TILE_ELEMS) && ((unsigned)gy < (unsigned)H) && ((unsigned)gx < (unsigned)W);
        off[k] = ok ? gy*W+gx : 0;
        if (ok) pmask |= (1u<<k);
    }

    // prologue: channel 0 directly into buf0
    #pragma unroll
    for (int k = 0; k < 9; ++k) {
        int i = tid + k*256;
        if (k < 8 || i < TILE_ELEMS)
            s_in[i] = (pmask>>k & 1) ? inB[off[k]] : 0.f;
    }
    // stage channel 1 into registers (written to buf1 at round 0)
    float stage[9];
    if (CIN > 1) {
        const float* src = inB + (size_t)HWl;
        #pragma unroll
        for (int k = 0; k < 9; ++k) {
            int i = tid + k*256;
            float v = 0.f;
            if ((k < 8 || i < TILE_ELEMS) && (pmask>>k & 1)) v = src[off[k]];
            stage[k] = v;
        }
    }
    __syncthreads();   // covers buf0 + half-0 weights

    const int tx  = tid & 31;
    const int wy4 = (tid >> 5)*4;

    ull acc[8][4];
    #pragma unroll
    for (int co = 0; co < 8; ++co)
        #pragma unroll
        for (int r = 0; r < 4; ++r) acc[co][r] = 0ull;

    for (int ci = 0; ci < CIN; ++ci) {
        // STS: channel ci+1 (staged last round / prologue) -> buf (ci+1)%3.
        // That buffer was last read at round ci-2; two barriers have passed.
        if (ci + 1 < CIN) {
            float* dst = s_in + ((ci+1)%3)*TILE_ELEMS;
            #pragma unroll
            for (int k = 0; k < 9; ++k) {
                int i = tid + k*256;
                if (k < 8 || i < TILE_ELEMS) dst[i] = stage[k];
            }
        }
        // LDG: channel ci+2 -> stage regs (consumed by STS next round)
        if (ci + 2 < CIN) {
            const float* src = inB + (size_t)(ci+2)*HWl;
            #pragma unroll
            for (int k = 0; k < 9; ++k) {
                int i = tid + k*256;
                float v = 0.f;
                if ((k < 8 || i < TILE_ELEMS) && (pmask>>k & 1)) v = src[off[k]];
                stage[k] = v;
            }
        }

        // compute from buf ci%3
        const float* buf = s_in + (ci%3)*TILE_ELEMS;
        ull P[6][3];
        #pragma unroll
        for (int rr = 0; rr < 6; ++rr) {
            const float* row = buf + (wy4 + rr)*66 + 2*tx;
            float2 u01 = *(const float2*)(row);
            float2 u23 = *(const float2*)(row + 2);
            P[rr][0] = pack2(u01.x, u01.y);
            P[rr][1] = pack2(u01.y, u23.x);
            P[rr][2] = pack2(u23.x, u23.y);
        }

        const ull* wci = s_w + (ci % HALF)*72;
        #pragma unroll
        for (int co = 0; co < 8; ++co) {
            #pragma unroll
            for (int ky = 0; ky < 3; ++ky)
                #pragma unroll
                for (int kx = 0; kx < 3; ++kx) {
                    ull wd = wci[co*9 + ky*3 + kx];
                    fma2(acc[co][0], wd, P[ky+0][kx]);
                    fma2(acc[co][1], wd, P[ky+1][kx]);
                    fma2(acc[co][2], wd, P[ky+2][kx]);
                    fma2(acc[co][3], wd, P[ky+3][kx]);
                }
        }
        __syncthreads();

        // at a half boundary, reload weights for the next HALF channels
        if (HALF < CIN && (ci % HALF) == HALF-1 && ci + 1 < CIN) {
            for (int i = tid; i < HALF*72; i += 256) {
                int cl = i / 72, r = i - cl*72;
                int co = r / 9,  t = r - co*9;
                float w = wgf.get(cg*8 + co, ci + 1 + cl, t);
                s_w[i] = pack2(w, w);
            }
            __syncthreads();
        }
    }

    // epilogue: bias (+relu), float2 store (W even, x0+2tx even)
    #pragma unroll
    for (int co = 0; co < 8; ++co) {
        int cout = cg*8 + co;
        if (cout >= coutTotal) break;
        float bb = biasLocal[co];
        float* outC = outBase + (size_t)cout*HWl;
        int gx = x0 + 2*tx;
        if (gx >= W) continue;
        #pragma unroll
        for (int r = 0; r < 4; ++r) {
            int gy = y0 + wy4 + r;
            if (gy >= H) continue;
            float2 v = unpack2(acc[co][r]);
            v.x += bb; v.y += bb;
            if (RELU) { v.x = fmaxf(v.x, 0.f); v.y = fmaxf(v.y, 0.f); }
            *(float2*)(outC + (size_t)gy*W + gx) = v;
        }
    }
}

// standard conv
template<int CIN, bool RELU>
__global__ __launch_bounds__(256, 2)
void conv3x3_k(const float* __restrict__ in, const float* __restrict__ wgt,
               const float* __restrict__ bias, float* __restrict__ out,
               int H, int W, int coutTotal, int wCinStride, int tilesX)
{
    constexpr int HALF = (CIN > 32) ? 32 : CIN;
    __shared__ __align__(16) float s_in[3*TILE_ELEMS];
    __shared__ ull s_w[HALF*72];

    const int cg = blockIdx.x;
    const int x0 = (blockIdx.y % tilesX) * 64;
    const int y0 = (blockIdx.y / tilesX) * 32;
    const int b  = blockIdx.z;

    WStd wg{wgt, wCinStride, coutTotal};
    conv_core<CIN, RELU>(in + (size_t)b*CIN*H*W, wg, bias + cg*8,
                         out + (size_t)b*coutTotal*H*W,
                         H, W, x0, y0, coutTotal, cg, s_in, s_w);
}

// fused heads conv: 30 couts (aff 24, gate 3, curv 3) in one pass
__global__ __launch_bounds__(256, 2)
void convheads_k(const float* __restrict__ in,
                 const float* __restrict__ aw, const float* __restrict__ ab,
                 const float* __restrict__ gw, const float* __restrict__ gb,
                 const float* __restrict__ cw, const float* __restrict__ cb,
                 float* __restrict__ out, int H, int W, int tilesX)
{
    __shared__ __align__(16) float s_in[3*TILE_ELEMS];
    __shared__ ull s_w[32*72];
    __shared__ float s_bias[8];

    const int cg = blockIdx.x;           // 0..3
    const int x0 = (blockIdx.y % tilesX) * 64;
    const int y0 = (blockIdx.y / tilesX) * 32;
    const int b  = blockIdx.z;

    if (threadIdx.x < 8) {
        int c = cg*8 + (int)threadIdx.x;
        float bv = 0.f;
        if (c < 24)      bv = ab[c];
        else if (c < 27) bv = gb[c-24];
        else if (c < 30) bv = cb[c-27];
        s_bias[threadIdx.x] = bv;
    }
    // s_bias is read only in the epilogue, after many __syncthreads

    WHeads wg{aw, gw, cw};
    conv_core<64, false>(in + (size_t)b*64*H*W, wg, s_bias,
                         out + (size_t)b*30*H*W,
                         H, W, x0, y0, 30, cg, s_in, s_w);
}

// ============================================================================
// Post-process heads -> fused step-invariant propagation coefficients.
// heads layout: planes 0-23 aff, 24-26 gate, 27-29 curv (64-ch part only)
// ============================================================================
__global__ void postproc_k(const float* __restrict__ heads, const float* __restrict__ cw,
                           const float* __restrict__ xin, const float* __restrict__ D,
                           float* __restrict__ coef, int Hs, int Ws)
{
    int HWs = Hs*Ws;
    int idx = blockIdx.x*blockDim.x + threadIdx.x;
    if (idx >= BB*HWs) return;
    int b = idx / HWs, p = idx - b*HWs;
    int y = p / Ws,    x = p - y*Ws;

    float An[24];
    #pragma unroll
    for (int k = 0; k < 3; ++k) {
        float s1 = 0.f;
        #pragma unroll
        for (int j = 0; j < 8; ++j) {
            float v = heads[(size_t)(b*30 + k*8 + j)*HWs + p];
            An[k*8+j] = v;
            s1 += fabsf(v);
        }
        float inv = 1.0f/(s1 + 1e-6f);
        #pragma unroll
        for (int j = 0; j < 8; ++j) An[k*8+j] *= inv;
    }

    float g0 = heads[(size_t)(b*30+24)*HWs + p];
    float g1 = heads[(size_t)(b*30+25)*HWs + p];
    float g2 = heads[(size_t)(b*30+26)*HWs + p];
    float mx = fmaxf(g0, fmaxf(g1, g2));
    float e0 = expf(g0-mx), e1 = expf(g1-mx), e2 = expf(g2-mx);
    float einv = 1.0f/(e0+e1+e2);
    float sig[3] = {e0*einv, e1*einv, e2*einv};

    const float* Db = D + (size_t)b*HWs;
    float sk[3];
    #pragma unroll
    for (int k = 0; k < 3; ++k) {
        float cr = heads[(size_t)(b*30+27+k)*HWs + p];
        #pragma unroll
        for (int ky = 0; ky < 3; ++ky) {
            int yy = y + ky - 1;
            if (yy < 0 || yy >= Hs) continue;
            #pragma unroll
            for (int kx = 0; kx < 3; ++kx) {
                int xx = x + kx - 1;
                if (xx < 0 || xx >= Ws) continue;
                cr += cw[(size_t)(k*65 + 64)*9 + ky*3 + kx] * (Db[yy*Ws + xx]*0.1f);
            }
        }
        float kap = 0.1f + 0.9f/(1.0f + expf(-cr));
        sk[k] = sig[k]*kap;
    }

    float mls = xin[(size_t)(b*6+4)*HWs + p];
    float dls = xin[(size_t)(b*6+3)*HWs + p];
    float m   = 0.9f*mls;
    float one = 1.0f - m;
    float Wsum = 0.f;
    #pragma unroll
    for (int k = 0; k < 3; ++k)
        #pragma unroll
        for (int j = 0; j < 8; ++j) {
            float Wv = sk[k]*An[k*8+j];
            Wsum += Wv;
            coef[(size_t)(b*26 + 1 + k*8 + j)*HWs + p] = one*Wv;
        }
    coef[(size_t)(b*26)*HWs + p]      = one*(1.0f - Wsum);
    coef[(size_t)(b*26 + 25)*HWs + p] = m*dls;
}

// ============================================================================
// One propagation step: 25-tap stencil with precomputed coefficients.
// ============================================================================
__global__ void prop_k(const float* __restrict__ Din, const float* __restrict__ coef,
                       float* __restrict__ Dout, int Hs, int Ws)
{
    __shared__ float sD[24][40];
    const int b  = blockIdx.z;
    const int x0 = blockIdx.x*32, y0 = blockIdx.y*16;
    const int HWs = Hs*Ws;
    const float* Db = Din + (size_t)b*HWs;

    int tid = threadIdx.y*32 + threadIdx.x;
    for (int i = tid; i < 24*40; i += 512) {
        int yy = i / 40, xx = i - yy*40;
        int gy = y0 + yy - 4, gx = x0 + xx - 4;
        sD[yy][xx] = ((unsigned)gy < (unsigned)Hs && (unsigned)gx < (unsigned)Ws)
                   ? Db[gy*Ws + gx] : 0.f;
    }
    __syncthreads();

    int x = x0 + threadIdx.x, y = y0 + threadIdx.y;
    if (x >= Ws || y >= Hs) return;
    int p = y*Ws + x;
    const float* cf = coef + (size_t)b*26*HWs;

    const int dyo[8] = {-1,-1,-1, 0, 0, 1, 1, 1};
    const int dxo[8] = {-1, 0, 1,-1, 1,-1, 0, 1};

    float acc = cf[p] * sD[threadIdx.y+4][threadIdx.x+4];
    #pragma unroll
    for (int k = 0; k < 3; ++k) {
        int d = 1 << k;
        #pragma unroll
        for (int j = 0; j < 8; ++j) {
            acc = fmaf(cf[(size_t)(1 + k*8 + j)*HWs + p],
                       sD[threadIdx.y + 4 + dyo[j]*d][threadIdx.x + 4 + dxo[j]*d],
                       acc);
        }
    }
    Dout[(size_t)b*HWs + p] = acc + cf[(size_t)25*HWs + p];
}

// ============================================================================
extern "C" void kernel_launch(void* const* d_in, const int* in_sizes, int n_in,
                              void* d_out, int out_size)
{
    const float* I   = (const float*)d_in[0];
    const float* DL  = (const float*)d_in[1];
    const float* ML  = (const float*)d_in[2];
    const float* E   = (const float*)d_in[3];
    const float* ew0 = (const float*)d_in[4];
    const float* eb0 = (const float*)d_in[5];
    const float* ew1 = (const float*)d_in[6];
    const float* eb1 = (const float*)d_in[7];
    const float* ew2 = (const float*)d_in[8];
    const float* eb2 = (const float*)d_in[9];
    const float* aw  = (const float*)d_in[10];
    const float* ab  = (const float*)d_in[11];
    const float* gw  = (const float*)d_in[12];
    const float* gb  = (const float*)d_in[13];
    const float* cw  = (const float*)d_in[14];
    const float* cbp = (const float*)d_in[15];

    float *xin, *f0, *f1, *heads, *coef, *Db, *D2, *Dp;
    cudaGetSymbolAddress((void**)&xin,   g_xin);
    cudaGetSymbolAddress((void**)&f0,    g_f0);
    cudaGetSymbolAddress((void**)&f1,    g_f1);
    cudaGetSymbolAddress((void**)&heads, g_heads);
    cudaGetSymbolAddress((void**)&coef,  g_coef);
    cudaGetSymbolAddress((void**)&Db,    g_D);
    cudaGetSymbolAddress((void**)&D2,    g_D2);
    cudaGetSymbolAddress((void**)&Dp,    g_Dp);

    const int scales[3] = {4, 2, 1};
    for (int si = 0; si < 3; ++si) {
        int s = scales[si];
        int Hs = HH / s, Ws = WW / s, HWs = Hs*Ws;
        int n = BB*HWs;
        int tpb = 256, nb = (n + tpb - 1)/tpb;

        if (si > 0) {
            int sp = scales[si-1];
            cudaMemcpyAsync(Dp, Db, sizeof(float)*(size_t)BB*(HH/sp)*(WW/sp),
                            cudaMemcpyDeviceToDevice);
        }

        if (s == 4)      prep_scale_k<4><<<nb, tpb>>>(I, DL, ML, E, xin, Db, Hs, Ws, 1);
        else if (s == 2) prep_scale_k<2><<<nb, tpb>>>(I, DL, ML, E, xin, Db, Hs, Ws, 0);
        else             prep_copy_k<<<nb, tpb>>>(I, DL, ML, E, xin);

        if (si > 0) blend_k<<<nb, tpb>>>(xin, Dp, Db, Hs, Ws);

        int tilesX = (Ws + 63)/64, tilesY = (Hs + 31)/32;
        dim3 blk(256);
        dim3 cgMain(8, tilesX*tilesY, BB);
        conv3x3_k<6,  true ><<<cgMain, blk>>>(xin, ew0, eb0, f0, Hs, Ws, 64, 6,  tilesX);
        conv3x3_k<64, true ><<<cgMain, blk>>>(f0,  ew1, eb1, f1, Hs, Ws, 64, 64, tilesX);
        conv3x3_k<64, true ><<<cgMain, blk>>>(f1,  ew2, eb2, f0, Hs, Ws, 64, 64, tilesX);
        dim3 cgHeads(4, tilesX*tilesY, BB);
        convheads_k<<<cgHeads, blk>>>(f0, aw, ab, gw, gb, cw, cbp,
                                      heads, Hs, Ws, tilesX);

        postproc_k<<<nb, tpb>>>(heads, cw, xin, Db, coef, Hs, Ws);

        dim3 pb(32, 16);
        dim3 pg((Ws+31)/32, (Hs+15)/16, BB);
        for (int t = 0; t < 6; ++t) {
            const float* src = (t & 1) ? D2 : Db;
            float*       dst = (t & 1) ? Db : D2;
            prop_k<<<pg, pb>>>(src, coef, dst, Hs, Ws);
        }
    }

    cudaMemcpyAsync(d_out, Db, sizeof(float)*(size_t)BB*HW1, cudaMemcpyDeviceToDevice);
}

// round 8
// speedup vs baseline: 1.7368x; 1.3050x over previous
#include <cuda_runtime.h>
#include <math.h>

// Problem constants (fixed by the dataset)
#define BB  2
#define HH  480
#define WW  640
#define HW1 (HH*WW)

// ---------------- scratch (static device memory; no allocations) ----------------
__device__ float g_xin  [BB*6 *HW1];
__device__ float g_f0   [BB*64*HW1];
__device__ float g_f1   [BB*64*HW1];
__device__ float g_heads[BB*30*HW1];   // 0-23 aff, 24-26 gate, 27-29 curv
__device__ float g_coef [BB*26*HW1];
__device__ float g_D    [BB*HW1];
__device__ float g_D2   [BB*HW1];
__device__ float g_Dp   [BB*HW1];

#define TILE_ELEMS 2244          // 34*66

// ============================================================================
// prep for s in {4,2}: antialiased triangle resize of I,E + valid-mean pool
// ============================================================================
template<int R>
__global__ void prep_scale_k(const float* __restrict__ I, const float* __restrict__ DL,
                             const float* __restrict__ ML, const float* __restrict__ E,
                             float* __restrict__ xin, float* __restrict__ Dout,
                             int Hs, int Ws, int writeD)
{
    int HWs = Hs*Ws;
    int idx = blockIdx.x*blockDim.x + threadIdx.x;
    if (idx >= BB*HWs) return;
    int b = idx / HWs, p = idx - b*HWs;
    int y = p / Ws,    x = p - y*Ws;

    float wy[2*R], wx[2*R];
    int   jy[2*R], jx[2*R];
    {
        float c = (y + 0.5f)*(float)R - 0.5f;
        int j0 = (int)ceilf(c - (float)R);
        float s = 0.f;
        #pragma unroll
        for (int t = 0; t < 2*R; ++t) {
            int j = j0 + t;
            float wt = 1.0f - fabsf((float)j - c)*(1.0f/(float)R);
            if (j < 0 || j >= HH || wt < 0.f) wt = 0.f;
            wy[t] = wt; s += wt;
            jy[t] = min(max(j,0), HH-1);
        }
        float inv = 1.0f/s;
        #pragma unroll
        for (int t = 0; t < 2*R; ++t) wy[t] *= inv;
    }
    {
        float c = (x + 0.5f)*(float)R - 0.5f;
        int j0 = (int)ceilf(c - (float)R);
        float s = 0.f;
        #pragma unroll
        for (int t = 0; t < 2*R; ++t) {
            int j = j0 + t;
            float wt = 1.0f - fabsf((float)j - c)*(1.0f/(float)R);
            if (j < 0 || j >= WW || wt < 0.f) wt = 0.f;
            wx[t] = wt; s += wt;
            jx[t] = min(max(j,0), WW-1);
        }
        float inv = 1.0f/s;
        #pragma unroll
        for (int t = 0; t < 2*R; ++t) wx[t] *= inv;
    }

    #pragma unroll
    for (int ch = 0; ch < 3; ++ch) {
        const float* src = I + (size_t)(b*3+ch)*HW1;
        float a = 0.f;
        #pragma unroll
        for (int ty = 0; ty < 2*R; ++ty) {
            if (wy[ty] == 0.f) continue;
            const float* row = src + jy[ty]*WW;
            float rs = 0.f;
            #pragma unroll
            for (int t = 0; t < 2*R; ++t) rs += wx[t]*row[jx[t]];
            a += wy[ty]*rs;
        }
        xin[(size_t)(b*6+ch)*HWs + p] = a;
    }
    {
        const float* src = E + (size_t)b*HW1;
        float a = 0.f;
        #pragma unroll
        for (int ty = 0; ty < 2*R; ++ty) {
            if (wy[ty] == 0.f) continue;
            const float* row = src + jy[ty]*WW;
            float rs = 0.f;
            #pragma unroll
            for (int t = 0; t < 2*R; ++t) rs += wx[t]*row[jx[t]];
            a += wy[ty]*rs;
        }
        a = fminf(fmaxf(a, 0.f), 1.f);
        xin[(size_t)(b*6+5)*HWs + p] = a;
        if (writeD) Dout[(size_t)b*HWs + p] = fminf(fmaxf(a*10.f, 0.f), 10.f);
    }
    {
        const float* dlb = DL + (size_t)b*HW1;
        const float* mlb = ML + (size_t)b*HW1;
        float ssum = 0.f, cnt = 0.f;
        #pragma unroll
        for (int iy = 0; iy < R; ++iy) {
            int gy = y*R + iy;
            #pragma unroll
            for (int ix = 0; ix < R; ++ix) {
                int gi = gy*WW + x*R + ix;
                float m = (mlb[gi] > 0.f) ? 1.f : 0.f;
                cnt  += m;
                ssum += dlb[gi]*m;
            }
        }
        float mls = (cnt > 0.f) ? 1.f : 0.f;
        float dls = (cnt > 0.f) ? ssum/(cnt + 1e-6f) : 0.f;
        xin[(size_t)(b*6+3)*HWs + p] = dls;
        xin[(size_t)(b*6+4)*HWs + p] = mls;
    }
}

__global__ void prep_copy_k(const float* __restrict__ I, const float* __restrict__ DL,
                            const float* __restrict__ ML, const float* __restrict__ E,
                            float* __restrict__ xin)
{
    int idx = blockIdx.x*blockDim.x + threadIdx.x;
    if (idx >= BB*HW1) return;
    int b = idx / HW1, p = idx - b*HW1;
    #pragma unroll
    for (int ch = 0; ch < 3; ++ch)
        xin[(size_t)(b*6+ch)*HW1 + p] = I[(size_t)(b*3+ch)*HW1 + p];
    xin[(size_t)(b*6+3)*HW1 + p] = DL[(size_t)b*HW1 + p];
    xin[(size_t)(b*6+4)*HW1 + p] = (ML[(size_t)b*HW1 + p] > 0.f) ? 1.f : 0.f;
    xin[(size_t)(b*6+5)*HW1 + p] = fminf(fmaxf(E[(size_t)b*HW1 + p], 0.f), 1.f);
}

// ============================================================================
__global__ void blend_k(const float* __restrict__ xin, const float* __restrict__ Dprev,
                        float* __restrict__ D, int Hs, int Ws)
{
    int HWs = Hs*Ws;
    int idx = blockIdx.x*blockDim.x + threadIdx.x;
    if (idx >= BB*HWs) return;
    int b = idx / HWs, p = idx - b*HWs;
    int y = p / Ws,    x = p - y*Ws;

    const float* Ep = xin + (size_t)(b*6+5)*HWs;
    float e  = Ep[p];
    float gx = (x > 0) ? e - Ep[p-1]  : 0.f;
    float gy = (y > 0) ? e - Ep[p-Ws] : 0.f;
    float g  = fminf((fabsf(gx) + fabsf(gy))*0.5f, 1.f);
    float wgt = 0.7f * fminf(fmaxf(1.f - g*10.0f, 0.f), 1.f);

    int Hp = Hs >> 1, Wp = Ws >> 1;
    float cy = 0.5f*(float)y - 0.25f;
    int  jy0 = (int)floorf(cy); float fy = cy - (float)jy0;
    int  ya = max(jy0, 0), yb = min(jy0+1, Hp-1);
    float cx = 0.5f*(float)x - 0.25f;
    int  jx0 = (int)floorf(cx); float fx = cx - (float)jx0;
    int  xa = max(jx0, 0), xb = min(jx0+1, Wp-1);

    const float* Dp = Dprev + (size_t)b*Hp*Wp;
    float up = (1.f-fy)*((1.f-fx)*Dp[ya*Wp+xa] + fx*Dp[ya*Wp+xb])
             +       fy*((1.f-fx)*Dp[yb*Wp+xa] + fx*Dp[yb*Wp+xb]);
    float P = fminf(fmaxf(e*10.f, 0.f), 10.f);
    D[(size_t)b*HWs + p] = wgt*up + (1.f - wgt)*P;
}

// ============================================================================
// Weight getters (global memory layout differs per conv)
// ============================================================================
struct WStd {
    const float* w; int stride; int coutTotal;
    __device__ __forceinline__ float get(int cout, int ci, int t) const {
        return (cout < coutTotal) ? w[((size_t)cout*stride + ci)*9 + t] : 0.f;
    }
};
struct WHeads {
    const float* aw; const float* gw; const float* cwp;
    __device__ __forceinline__ float get(int c, int ci, int t) const {
        if (c < 24) return aw[((size_t)c*64       + ci)*9 + t];
        if (c < 27) return gw[((size_t)(c-24)*64  + ci)*9 + t];
        if (c < 30) return cwp[((size_t)(c-27)*65 + ci)*9 + t];
        return 0.f;
    }
};

// ============================================================================
// conv core: 64x32 output tile, 8 couts/block, PLAIN fp32 FFMA (no f32x2 —
// that is a sm_103a feature; on sm_100a ptxas emulates it at 3x cost).
// - input: 2-buffer register-staged double buffer (R6-proven)
// - weights: ALL CIN*72 scalar floats preloaded to smem once (18.4KB max)
// - P: 6 halo rows x 4 floats per thread, reused across ky and both columns
// biasLocal is indexed by co (0..7); caller pre-offsets.
// ============================================================================
template<int CIN, bool RELU, typename WG>
__device__ __forceinline__
void conv_core(const float* __restrict__ inB, WG wgf,
               const float* __restrict__ biasLocal,
               float* __restrict__ outBase,
               int H, int W, int x0, int y0, int coutTotal, int cg,
               float* __restrict__ s_in, float* __restrict__ s_w)
{
    const int HWl = H*W;
    const int tid = threadIdx.x;

    // preload ALL weights for this block's 8 couts (scalar fp32)
    for (int i = tid; i < CIN*72; i += 256) {
        int ci = i / 72, r = i - ci*72;
        int co = r / 9,  t = r - co*9;
        s_w[i] = wgf.get(cg*8 + co, ci, t);
    }

    // per-thread tile-load geometry (9 slots)
    int off[9]; unsigned pmask = 0;
    #pragma unroll
    for (int k = 0; k < 9; ++k) {
        int i = tid + k*256;
        int yy = i/66, xx = i - yy*66;
        int gy = y0+yy-1, gx = x0+xx-1;
        bool ok = (i < TILE_ELEMS) && ((unsigned)gy < (unsigned)H) && ((unsigned)gx < (unsigned)W);
        off[k] = ok ? gy*W+gx : 0;
        if (ok) pmask |= (1u<<k);
    }

    // prologue: channel 0 -> buf0
    #pragma unroll
    for (int k = 0; k < 9; ++k) {
        int i = tid + k*256;
        if (k < 8 || i < TILE_ELEMS)
            s_in[i] = (pmask>>k & 1) ? inB[off[k]] : 0.f;
    }
    __syncthreads();   // covers buf0 + weights

    const int tx  = tid & 31;
    const int wy4 = (tid >> 5)*4;

    float acc[8][4][2];
    #pragma unroll
    for (int co = 0; co < 8; ++co)
        #pragma unroll
        for (int r = 0; r < 4; ++r) { acc[co][r][0] = 0.f; acc[co][r][1] = 0.f; }

    for (int ci = 0; ci < CIN; ++ci) {
        const int cur = ci & 1;

        // stage next channel into registers (overlaps with compute)
        float stage[9];
        if (ci + 1 < CIN) {
            const float* src = inB + (size_t)(ci+1)*HWl;
            #pragma unroll
            for (int k = 0; k < 9; ++k) {
                int i = tid + k*256;
                float v = 0.f;
                if ((k < 8 || i < TILE_ELEMS) && (pmask>>k & 1)) v = src[off[k]];
                stage[k] = v;
            }
        }

        // load 6 halo rows x 4 floats (cols 2tx .. 2tx+3 in halo coords)
        const float* buf = s_in + cur*TILE_ELEMS;
        float P[6][4];
        #pragma unroll
        for (int rr = 0; rr < 6; ++rr) {
            const float* row = buf + (wy4 + rr)*66 + 2*tx;
            float2 a = *(const float2*)(row);
            float2 b = *(const float2*)(row + 2);
            P[rr][0] = a.x; P[rr][1] = a.y; P[rr][2] = b.x; P[rr][3] = b.y;
        }

        const float* wci = s_w + ci*72;
        #pragma unroll
        for (int co = 0; co < 8; ++co) {
            #pragma unroll
            for (int ky = 0; ky < 3; ++ky) {
                #pragma unroll
                for (int kx = 0; kx < 3; ++kx) {
                    float w = wci[co*9 + ky*3 + kx];
                    #pragma unroll
                    for (int r = 0; r < 4; ++r) {
                        acc[co][r][0] = fmaf(w, P[r+ky][kx],   acc[co][r][0]);
                        acc[co][r][1] = fmaf(w, P[r+ky][kx+1], acc[co][r][1]);
                    }
                }
            }
        }

        // write staged tile into the other buffer
        if (ci + 1 < CIN) {
            float* dst = s_in + (cur^1)*TILE_ELEMS;
            #pragma unroll
            for (int k = 0; k < 9; ++k) {
                int i = tid + k*256;
                if (k < 8 || i < TILE_ELEMS) dst[i] = stage[k];
            }
        }
        __syncthreads();
    }

    // epilogue: bias (+relu), float2 store (W even, x0+2tx even)
    #pragma unroll
    for (int co = 0; co < 8; ++co) {
        int cout = cg*8 + co;
        if (cout >= coutTotal) break;
        float bb = biasLocal[co];
        float* outC = outBase + (size_t)cout*HWl;
        int gx = x0 + 2*tx;
        if (gx >= W) continue;
        #pragma unroll
        for (int r = 0; r < 4; ++r) {
            int gy = y0 + wy4 + r;
            if (gy >= H) continue;
            float2 v;
            v.x = acc[co][r][0] + bb;
            v.y = acc[co][r][1] + bb;
            if (RELU) { v.x = fmaxf(v.x, 0.f); v.y = fmaxf(v.y, 0.f); }
            *(float2*)(outC + (size_t)gy*W + gx) = v;
        }
    }
}

// standard conv
template<int CIN, bool RELU>
__global__ __launch_bounds__(256, 2)
void conv3x3_k(const float* __restrict__ in, const float* __restrict__ wgt,
               const float* __restrict__ bias, float* __restrict__ out,
               int H, int W, int coutTotal, int wCinStride, int tilesX)
{
    __shared__ __align__(16) float s_in[2*TILE_ELEMS];
    __shared__ float s_w[CIN*72];

    const int cg = blockIdx.x;
    const int x0 = (blockIdx.y % tilesX) * 64;
    const int y0 = (blockIdx.y / tilesX) * 32;
    const int b  = blockIdx.z;

    WStd wg{wgt, wCinStride, coutTotal};
    conv_core<CIN, RELU>(in + (size_t)b*CIN*H*W, wg, bias + cg*8,
                         out + (size_t)b*coutTotal*H*W,
                         H, W, x0, y0, coutTotal, cg, s_in, s_w);
}

// fused heads conv: 30 couts (aff 24, gate 3, curv 3) in one pass
__global__ __launch_bounds__(256, 2)
void convheads_k(const float* __restrict__ in,
                 const float* __restrict__ aw, const float* __restrict__ ab,
                 const float* __restrict__ gw, const float* __restrict__ gb,
                 const float* __restrict__ cw, const float* __restrict__ cb,
                 float* __restrict__ out, int H, int W, int tilesX)
{
    __shared__ __align__(16) float s_in[2*TILE_ELEMS];
    __shared__ float s_w[64*72];
    __shared__ float s_bias[8];

    const int cg = blockIdx.x;           // 0..3
    const int x0 = (blockIdx.y % tilesX) * 64;
    const int y0 = (blockIdx.y / tilesX) * 32;
    const int b  = blockIdx.z;

    if (threadIdx.x < 8) {
        int c = cg*8 + (int)threadIdx.x;
        float bv = 0.f;
        if (c < 24)      bv = ab[c];
        else if (c < 27) bv = gb[c-24];
        else if (c < 30) bv = cb[c-27];
        s_bias[threadIdx.x] = bv;
    }
    // s_bias is read only in the epilogue, after many __syncthreads

    WHeads wg{aw, gw, cw};
    conv_core<64, false>(in + (size_t)b*64*H*W, wg, s_bias,
                         out + (size_t)b*30*H*W,
                         H, W, x0, y0, 30, cg, s_in, s_w);
}

// ============================================================================
// Post-process heads -> fused step-invariant propagation coefficients.
// heads layout: planes 0-23 aff, 24-26 gate, 27-29 curv (64-ch part only)
// ============================================================================
__global__ void postproc_k(const float* __restrict__ heads, const float* __restrict__ cw,
                           const float* __restrict__ xin, const float* __restrict__ D,
                           float* __restrict__ coef, int Hs, int Ws)
{
    int HWs = Hs*Ws;
    int idx = blockIdx.x*blockDim.x + threadIdx.x;
    if (idx >= BB*HWs) return;
    int b = idx / HWs, p = idx - b*HWs;
    int y = p / Ws,    x = p - y*Ws;

    float An[24];
    #pragma unroll
    for (int k = 0; k < 3; ++k) {
        float s1 = 0.f;
        #pragma unroll
        for (int j = 0; j < 8; ++j) {
            float v = heads[(size_t)(b*30 + k*8 + j)*HWs + p];
            An[k*8+j] = v;
            s1 += fabsf(v);
        }
        float inv = 1.0f/(s1 + 1e-6f);
        #pragma unroll
        for (int j = 0; j < 8; ++j) An[k*8+j] *= inv;
    }

    float g0 = heads[(size_t)(b*30+24)*HWs + p];
    float g1 = heads[(size_t)(b*30+25)*HWs + p];
    float g2 = heads[(size_t)(b*30+26)*HWs + p];
    float mx = fmaxf(g0, fmaxf(g1, g2));
    float e0 = expf(g0-mx), e1 = expf(g1-mx), e2 = expf(g2-mx);
    float einv = 1.0f/(e0+e1+e2);
    float sig[3] = {e0*einv, e1*einv, e2*einv};

    const float* Db = D + (size_t)b*HWs;
    float sk[3];
    #pragma unroll
    for (int k = 0; k < 3; ++k) {
        float cr = heads[(size_t)(b*30+27+k)*HWs + p];
        #pragma unroll
        for (int ky = 0; ky < 3; ++ky) {
            int yy = y + ky - 1;
            if (yy < 0 || yy >= Hs) continue;
            #pragma unroll
            for (int kx = 0; kx < 3; ++kx) {
                int xx = x + kx - 1;
                if (xx < 0 || xx >= Ws) continue;
                cr += cw[(size_t)(k*65 + 64)*9 + ky*3 + kx] * (Db[yy*Ws + xx]*0.1f);
            }
        }
        float kap = 0.1f + 0.9f/(1.0f + expf(-cr));
        sk[k] = sig[k]*kap;
    }

    float mls = xin[(size_t)(b*6+4)*HWs + p];
    float dls = xin[(size_t)(b*6+3)*HWs + p];
    float m   = 0.9f*mls;
    float one = 1.0f - m;
    float Wsum = 0.f;
    #pragma unroll
    for (int k = 0; k < 3; ++k)
        #pragma unroll
        for (int j = 0; j < 8; ++j) {
            float Wv = sk[k]*An[k*8+j];
            Wsum += Wv;
            coef[(size_t)(b*26 + 1 + k*8 + j)*HWs + p] = one*Wv;
        }
    coef[(size_t)(b*26)*HWs + p]      = one*(1.0f - Wsum);
    coef[(size_t)(b*26 + 25)*HWs + p] = m*dls;
}

// ============================================================================
// One propagation step: 25-tap stencil with precomputed coefficients.
// ============================================================================
__global__ void prop_k(const float* __restrict__ Din, const float* __restrict__ coef,
                       float* __restrict__ Dout, int Hs, int Ws)
{
    __shared__ float sD[24][40];
    const int b  = blockIdx.z;
    const int x0 = blockIdx.x*32, y0 = blockIdx.y*16;
    const int HWs = Hs*Ws;
    const float* Db = Din + (size_t)b*HWs;

    int tid = threadIdx.y*32 + threadIdx.x;
    for (int i = tid; i < 24*40; i += 512) {
        int yy = i / 40, xx = i - yy*40;
        int gy = y0 + yy - 4, gx = x0 + xx - 4;
        sD[yy][xx] = ((unsigned)gy < (unsigned)Hs && (unsigned)gx < (unsigned)Ws)
                   ? Db[gy*Ws + gx] : 0.f;
    }
    __syncthreads();

    int x = x0 + threadIdx.x, y = y0 + threadIdx.y;
    if (x >= Ws || y >= Hs) return;
    int p = y*Ws + x;
    const float* cf = coef + (size_t)b*26*HWs;

    const int dyo[8] = {-1,-1,-1, 0, 0, 1, 1, 1};
    const int dxo[8] = {-1, 0, 1,-1, 1,-1, 0, 1};

    float acc = cf[p] * sD[threadIdx.y+4][threadIdx.x+4];
    #pragma unroll
    for (int k = 0; k < 3; ++k) {
        int d = 1 << k;
        #pragma unroll
        for (int j = 0; j < 8; ++j) {
            acc = fmaf(cf[(size_t)(1 + k*8 + j)*HWs + p],
                       sD[threadIdx.y + 4 + dyo[j]*d][threadIdx.x + 4 + dxo[j]*d],
                       acc);
        }
    }
    Dout[(size_t)b*HWs + p] = acc + cf[(size_t)25*HWs + p];
}

// ============================================================================
extern "C" void kernel_launch(void* const* d_in, const int* in_sizes, int n_in,
                              void* d_out, int out_size)
{
    const float* I   = (const float*)d_in[0];
    const float* DL  = (const float*)d_in[1];
    const float* ML  = (const float*)d_in[2];
    const float* E   = (const float*)d_in[3];
    const float* ew0 = (const float*)d_in[4];
    const float* eb0 = (const float*)d_in[5];
    const float* ew1 = (const float*)d_in[6];
    const float* eb1 = (const float*)d_in[7];
    const float* ew2 = (const float*)d_in[8];
    const float* eb2 = (const float*)d_in[9];
    const float* aw  = (const float*)d_in[10];
    const float* ab  = (const float*)d_in[11];
    const float* gw  = (const float*)d_in[12];
    const float* gb  = (const float*)d_in[13];
    const float* cw  = (const float*)d_in[14];
    const float* cbp = (const float*)d_in[15];

    float *xin, *f0, *f1, *heads, *coef, *Db, *D2, *Dp;
    cudaGetSymbolAddress((void**)&xin,   g_xin);
    cudaGetSymbolAddress((void**)&f0,    g_f0);
    cudaGetSymbolAddress((void**)&f1,    g_f1);
    cudaGetSymbolAddress((void**)&heads, g_heads);
    cudaGetSymbolAddress((void**)&coef,  g_coef);
    cudaGetSymbolAddress((void**)&Db,    g_D);
    cudaGetSymbolAddress((void**)&D2,    g_D2);
    cudaGetSymbolAddress((void**)&Dp,    g_Dp);

    const int scales[3] = {4, 2, 1};
    for (int si = 0; si < 3; ++si) {
        int s = scales[si];
        int Hs = HH / s, Ws = WW / s, HWs = Hs*Ws;
        int n = BB*HWs;
        int tpb = 256, nb = (n + tpb - 1)/tpb;

        if (si > 0) {
            int sp = scales[si-1];
            cudaMemcpyAsync(Dp, Db, sizeof(float)*(size_t)BB*(HH/sp)*(WW/sp),
                            cudaMemcpyDeviceToDevice);
        }

        if (s == 4)      prep_scale_k<4><<<nb, tpb>>>(I, DL, ML, E, xin, Db, Hs, Ws, 1);
        else if (s == 2) prep_scale_k<2><<<nb, tpb>>>(I, DL, ML, E, xin, Db, Hs, Ws, 0);
        else             prep_copy_k<<<nb, tpb>>>(I, DL, ML, E, xin);

        if (si > 0) blend_k<<<nb, tpb>>>(xin, Dp, Db, Hs, Ws);

        int tilesX = (Ws + 63)/64, tilesY = (Hs + 31)/32;
        dim3 blk(256);
        dim3 cgMain(8, tilesX*tilesY, BB);
        conv3x3_k<6,  true ><<<cgMain, blk>>>(xin, ew0, eb0, f0, Hs, Ws, 64, 6,  tilesX);
        conv3x3_k<64, true ><<<cgMain, blk>>>(f0,  ew1, eb1, f1, Hs, Ws, 64, 64, tilesX);
        conv3x3_k<64, true ><<<cgMain, blk>>>(f1,  ew2, eb2, f0, Hs, Ws, 64, 64, tilesX);
        dim3 cgHeads(4, tilesX*tilesY, BB);
        convheads_k<<<cgHeads, blk>>>(f0, aw, ab, gw, gb, cw, cbp,
                                      heads, Hs, Ws, tilesX);

        postproc_k<<<nb, tpb>>>(heads, cw, xin, Db, coef, Hs, Ws);

        dim3 pb(32, 16);
        dim3 pg((Ws+31)/32, (Hs+15)/16, BB);
        for (int t = 0; t < 6; ++t) {
            const float* src = (t & 1) ? D2 : Db;
            float*       dst = (t & 1) ? Db : D2;
            prop_k<<<pg, pb>>>(src, coef, dst, Hs, Ws);
        }
    }

    cudaMemcpyAsync(d_out, Db, sizeof(float)*(size_t)BB*HW1, cudaMemcpyDeviceToDevice);
}